// round 1
// baseline (speedup 1.0000x reference)
#include <cuda_runtime.h>

#define BATCH 4
#define KDIM 1792
#define NPIX 4096
#define NCENT 4096
#define TOPK 200
#define PHI_OUT_C 896
#define SCORE_ELEMS (BATCH * TOPK * NPIX)   // 3,276,800 floats, then PHI slice

// ---------------- scratch (static device memory; no allocations) ----------------
__device__ float g_pool0[BATCH * 256 * 64 * 64];
__device__ float g_pool1[BATCH * 512 * 32 * 32];
__device__ float g_pool2[BATCH * 1024 * 16 * 16];
__device__ float g_conv1[BATCH * 512 * 32 * 32];
__device__ float g_conv2[BATCH * 1024 * 16 * 16];
__device__ float g_phi[(size_t)BATCH * NPIX * KDIM];   // (b, pix, chan) row-major
__device__ float g_feats[BATCH * NPIX];
__device__ float g_cents[NCENT];
__device__ float g_dist[(size_t)BATCH * NPIX * NCENT]; // 268 MB
__device__ float g_wT1[258 * 256];
__device__ float g_wT2[514 * 512];
__device__ float g_wT3[1026 * 1024];

// ---------------- level traits helpers ----------------
template <int L> struct Lv {
    static constexpr int C = (L == 0) ? 256 : (L == 1) ? 512 : 1024;
    static constexpr int H = (L == 0) ? 64 : (L == 1) ? 32 : 16;
    static constexpr int PIX = H * H;
    static constexpr int CHOFF = (L == 0) ? 0 : (L == 1) ? 256 : 768;
};

// ---------------- 1) weight transpose: w[o][k] -> wT[k][o] ----------------
template <int L>
__global__ void wtrans_kernel(const float* __restrict__ w) {
    constexpr int CO = Lv<L>::C;
    constexpr int KI = CO + 2;
    float* wT = (L == 0) ? g_wT1 : (L == 1) ? g_wT2 : g_wT3;
    int i = blockIdx.x * blockDim.x + threadIdx.x;
    if (i >= CO * KI) return;
    int o = i / KI, k = i % KI;
    wT[k * CO + o] = w[i];
}

// ---------------- 2) avg_pool 3x3 stride1 pad1, /9 (count_include_pad) ----------------
template <int L>
__global__ void pool3_kernel(const float* __restrict__ x) {
    constexpr int C = Lv<L>::C, H = Lv<L>::H;
    float* y = (L == 0) ? g_pool0 : (L == 1) ? g_pool1 : g_pool2;
    int i = blockIdx.x * blockDim.x + threadIdx.x;
    constexpr int total = BATCH * C * H * H;
    if (i >= total) return;
    int w = i % H;
    int h = (i / H) % H;
    int bc = i / (H * H);
    const float* p = x + (size_t)bc * H * H;
    float s = 0.f;
#pragma unroll
    for (int dh = -1; dh <= 1; ++dh) {
        int hh = h + dh;
        if ((unsigned)hh < (unsigned)H) {
            const float* r = p + hh * H;
#pragma unroll
            for (int dw = -1; dw <= 1; ++dw) {
                int ww = w + dw;
                if ((unsigned)ww < (unsigned)H) s += r[ww];
            }
        }
    }
    y[i] = s * (1.0f / 9.0f);
}

// ---------------- 3) CoordConv 1x1 as GEMM: out[pix][o] = sum_k pooled[k][pix]*wT[k][o] + coords + bias
// Tile: 64 pix x 64 out x 16 k, 256 threads, 4x4 per thread.
template <int L>
__global__ __launch_bounds__(256) void conv1x1_kernel(const float* __restrict__ bias,
                                                      float* __restrict__ out) {
    constexpr int CI = Lv<L>::C, CO = CI, H = Lv<L>::H, PIX = Lv<L>::PIX;
    const float* pooled = (L == 0) ? g_pool0 : (L == 1) ? g_pool1 : g_pool2;
    const float* wT = (L == 0) ? g_wT1 : (L == 1) ? g_wT2 : g_wT3;
    float* convout = (L == 1) ? g_conv1 : g_conv2;  // unused for L==0

    int b = blockIdx.z;
    int oT = blockIdx.x * 64, pT = blockIdx.y * 64;
    __shared__ float As[16][64];  // [k][pix]
    __shared__ float Bs[16][64];  // [k][o]
    int tid = threadIdx.x, tx = tid & 15, ty = tid >> 4;
    float acc[4][4] = {};
    const float* Ab = pooled + (size_t)b * CI * PIX;

    for (int kt = 0; kt < CI; kt += 16) {
        int lr = tid >> 4, lc = (tid & 15) * 4;
        *(float4*)&As[lr][lc] = *(const float4*)(Ab + (size_t)(kt + lr) * PIX + pT + lc);
        *(float4*)&Bs[lr][lc] = *(const float4*)(wT + (size_t)(kt + lr) * CO + oT + lc);
        __syncthreads();
#pragma unroll
        for (int k = 0; k < 16; k++) {
            float4 av = *(float4*)&As[k][ty * 4];
            float4 bv = *(float4*)&Bs[k][tx * 4];
            float a[4] = {av.x, av.y, av.z, av.w};
            float bb[4] = {bv.x, bv.y, bv.z, bv.w};
#pragma unroll
            for (int i2 = 0; i2 < 4; i2++)
#pragma unroll
                for (int j = 0; j < 4; j++) acc[i2][j] += a[i2] * bb[j];
        }
        __syncthreads();
    }

#pragma unroll
    for (int i2 = 0; i2 < 4; i2++) {
        int pix = pT + ty * 4 + i2;
        float xg = -1.0f + 2.0f * (float)(pix % H) / (float)(H - 1);
        float yg = -1.0f + 2.0f * (float)(pix / H) / (float)(H - 1);
#pragma unroll
        for (int j = 0; j < 4; j++) {
            int o = oT + tx * 4 + j;
            float v = acc[i2][j] + bias[o] + wT[(size_t)CI * CO + o] * xg +
                      wT[(size_t)(CI + 1) * CO + o] * yg;
            if (L == 0) {
                // 64x64 level: resize is identity -> write phi + output slice directly
                g_phi[((size_t)(b * NPIX) + pix) * KDIM + o] = v;
                out[SCORE_ELEMS + ((size_t)(b * PHI_OUT_C) + o) * NPIX + pix] = v;
            } else {
                convout[((size_t)(b * CO) + o) * PIX + pix] = v;
            }
        }
    }
}

// ---------------- 4) bilinear resize (half-pixel centers, edge clamp) ----------------
template <int L>
__global__ void resize_kernel(float* __restrict__ out) {
    constexpr int C = Lv<L>::C, H = Lv<L>::H, CHOFF = Lv<L>::CHOFF;
    const float* conv = (L == 1) ? g_conv1 : g_conv2;
    int idx = blockIdx.x * blockDim.x + threadIdx.x;
    constexpr int total = BATCH * C * 4096;
    if (idx >= total) return;
    int opix = idx & 4095;
    int t = idx >> 12;
    int o = t % C;
    int b = t / C;
    int ox = opix & 63, oy = opix >> 6;
    constexpr float scale = (float)H / 64.0f;
    float u = fmaxf((ox + 0.5f) * scale - 0.5f, 0.0f);
    float v = fmaxf((oy + 0.5f) * scale - 0.5f, 0.0f);
    int x0 = min((int)u, H - 1), y0 = min((int)v, H - 1);
    int x1 = min(x0 + 1, H - 1), y1 = min(y0 + 1, H - 1);
    float fx = u - (float)x0, fy = v - (float)y0;
    const float* p = conv + ((size_t)(b * C) + o) * (H * H);
    float v00 = p[y0 * H + x0], v01 = p[y0 * H + x1];
    float v10 = p[y1 * H + x0], v11 = p[y1 * H + x1];
    float val = (1.f - fy) * ((1.f - fx) * v00 + fx * v01) + fy * ((1.f - fx) * v10 + fx * v11);
    g_phi[((size_t)(b * NPIX) + opix) * KDIM + CHOFF + o] = val;
    int gc = CHOFF + o;
    if (gc < PHI_OUT_C)
        out[SCORE_ELEMS + ((size_t)(b * PHI_OUT_C) + gc) * NPIX + opix] = val;
}

// ---------------- 5) feats / cents ----------------
__global__ void feats_kernel() {
    int row = blockIdx.x;
    const float* p = g_phi + (size_t)row * KDIM;
    float s = 0.f;
    for (int k = threadIdx.x; k < KDIM; k += 256) {
        float v = p[k];
        s += v * v;
    }
    __shared__ float sh[256];
    sh[threadIdx.x] = s;
    __syncthreads();
    for (int off = 128; off > 0; off >>= 1) {
        if (threadIdx.x < off) sh[threadIdx.x] += sh[threadIdx.x + off];
        __syncthreads();
    }
    if (threadIdx.x == 0) g_feats[row] = sh[0];
}

__global__ void cents_kernel(const float* __restrict__ Cm) {
    int j = blockIdx.x * blockDim.x + threadIdx.x;
    if (j >= NCENT) return;
    float s = 0.f;
    for (int k = 0; k < KDIM; k++) {
        float v = Cm[(size_t)k * NCENT + j];
        s += v * v;
    }
    g_cents[j] = s;
}

// ---------------- 6) distance GEMM: dist[b][i][j] = sqrt(feats+cents-2*phi.C) ----------------
// 128x128x16 tile, 256 threads, 8x8 per thread.
__global__ __launch_bounds__(256) void dist_kernel(const float* __restrict__ Cm) {
    int b = blockIdx.z;
    int iT = blockIdx.y * 128;
    int jT = blockIdx.x * 128;
    __shared__ float As[16][132];  // [k][pix], padded
    __shared__ float Bs[16][128];  // [k][cent]
    const float* Ab = g_phi + (size_t)b * NPIX * KDIM;
    int tid = threadIdx.x, tx = tid & 15, ty = tid >> 4;
    float acc[8][8] = {};

    for (int kt = 0; kt < KDIM; kt += 16) {
#pragma unroll
        for (int pass = 0; pass < 2; pass++) {
            int row = pass * 64 + (tid >> 2);
            int kk = (tid & 3) * 4;
            float4 a = *(const float4*)(Ab + (size_t)(iT + row) * KDIM + kt + kk);
            As[kk][row] = a.x;
            As[kk + 1][row] = a.y;
            As[kk + 2][row] = a.z;
            As[kk + 3][row] = a.w;
        }
#pragma unroll
        for (int pass = 0; pass < 2; pass++) {
            int kk = pass * 8 + (tid >> 5);
            int jj = (tid & 31) * 4;
            *(float4*)&Bs[kk][jj] = *(const float4*)(Cm + (size_t)(kt + kk) * NCENT + jT + jj);
        }
        __syncthreads();
#pragma unroll
        for (int k = 0; k < 16; k++) {
            float a[8], bb[8];
            *(float4*)&a[0] = *(float4*)&As[k][ty * 8];
            *(float4*)&a[4] = *(float4*)&As[k][ty * 8 + 4];
            *(float4*)&bb[0] = *(float4*)&Bs[k][tx * 8];
            *(float4*)&bb[4] = *(float4*)&Bs[k][tx * 8 + 4];
#pragma unroll
            for (int i2 = 0; i2 < 8; i2++)
#pragma unroll
                for (int j = 0; j < 8; j++) acc[i2][j] += a[i2] * bb[j];
        }
        __syncthreads();
    }

    float* dbase = g_dist + (size_t)b * NPIX * NCENT;
#pragma unroll
    for (int i2 = 0; i2 < 8; i2++) {
        int gi = iT + ty * 8 + i2;
        float fi = g_feats[b * NPIX + gi];
        float* dst = dbase + (size_t)gi * NCENT + jT + tx * 8;
        float4 o0, o1;
        float tmp[8];
#pragma unroll
        for (int j = 0; j < 8; j++) {
            float d2 = fi + g_cents[jT + tx * 8 + j] - 2.0f * acc[i2][j];
            tmp[j] = sqrtf(fmaxf(d2, 0.0f));
        }
        o0 = make_float4(tmp[0], tmp[1], tmp[2], tmp[3]);
        o1 = make_float4(tmp[4], tmp[5], tmp[6], tmp[7]);
        *(float4*)dst = o0;
        *(float4*)(dst + 4) = o1;
    }
}

// ---------------- 7) top-200 smallest, sorted ascending, per row ----------------
// One block per (b, pixel): 4096 values in registers (16/thread).
// Binary search on float-as-uint key space for the exact 200th smallest T,
// gather (<T) + pad with T, bitonic sort 256, emit first 200.
__global__ __launch_bounds__(256) void select_kernel(float* __restrict__ out) {
    int row = blockIdx.x;
    int b = row >> 12;
    int pix = row & 4095;
    const float* d = g_dist + (size_t)row * NCENT;
    int t = threadIdx.x;

    unsigned key[16];
#pragma unroll
    for (int j = 0; j < 16; j++) key[j] = __float_as_uint(d[t + j * 256]);

    // block min / max
    unsigned mn = 0xFFFFFFFFu, mx = 0u;
#pragma unroll
    for (int j = 0; j < 16; j++) {
        mn = min(mn, key[j]);
        mx = max(mx, key[j]);
    }
    for (int off = 16; off; off >>= 1) {
        mn = min(mn, __shfl_down_sync(0xFFFFFFFFu, mn, off));
        mx = max(mx, __shfl_down_sync(0xFFFFFFFFu, mx, off));
    }
    __shared__ unsigned shmn[8], shmx[8];
    __shared__ unsigned s_lo, s_hi;
    if ((t & 31) == 0) {
        shmn[t >> 5] = mn;
        shmx[t >> 5] = mx;
    }
    __syncthreads();
    if (t == 0) {
        unsigned a = shmn[0], z = shmx[0];
        for (int w = 1; w < 8; w++) {
            a = min(a, shmn[w]);
            z = max(z, shmx[w]);
        }
        s_lo = a;
        s_hi = z;
    }
    __syncthreads();
    unsigned lo = s_lo, hi = s_hi;

    // binary search: smallest T with count(key <= T) >= TOPK  == exact 200th smallest
    __shared__ int shcnt[8];
    __shared__ int sh_total;
    while (lo < hi) {
        unsigned mid = lo + ((hi - lo) >> 1);
        int c = 0;
#pragma unroll
        for (int j = 0; j < 16; j++) c += (key[j] <= mid) ? 1 : 0;
        for (int off = 16; off; off >>= 1) c += __shfl_down_sync(0xFFFFFFFFu, c, off);
        if ((t & 31) == 0) shcnt[t >> 5] = c;
        __syncthreads();
        if (t == 0) {
            int s = 0;
            for (int w = 0; w < 8; w++) s += shcnt[w];
            sh_total = s;
        }
        __syncthreads();
        int total = sh_total;
        __syncthreads();
        if (total >= TOPK)
            hi = mid;
        else
            lo = mid + 1;
    }
    unsigned T = lo;

    // gather values < T (count <= 199), pad remaining slots with T
    __shared__ unsigned cand[256];
    __shared__ int s_cnt;
    cand[t] = T;
    if (t == 0) s_cnt = 0;
    __syncthreads();
#pragma unroll
    for (int j = 0; j < 16; j++) {
        if (key[j] < T) {
            int p = atomicAdd(&s_cnt, 1);
            if (p < 256) cand[p] = key[j];
        }
    }
    __syncthreads();

    // bitonic sort 256 ascending (uint keys == float order for non-negative floats)
    for (int k = 2; k <= 256; k <<= 1) {
        for (int j = k >> 1; j > 0; j >>= 1) {
            int ixj = t ^ j;
            if (ixj > t) {
                unsigned a = cand[t], z = cand[ixj];
                bool up = ((t & k) == 0);
                if ((a > z) == up) {
                    cand[t] = z;
                    cand[ixj] = a;
                }
            }
            __syncthreads();
        }
    }

    if (t < TOPK)
        out[((size_t)(b * TOPK) + t) * NPIX + pix] = __uint_as_float(cand[t]);
}

// ---------------- launch ----------------
extern "C" void kernel_launch(void* const* d_in, const int* in_sizes, int n_in,
                              void* d_out, int out_size) {
    const float* p0 = (const float*)d_in[0];
    const float* p1 = (const float*)d_in[1];
    const float* p2 = (const float*)d_in[2];
    // d_in[3] = label (unused), d_in[4] = mask (unused)
    const float* w1 = (const float*)d_in[5];
    const float* b1 = (const float*)d_in[6];
    const float* w2 = (const float*)d_in[7];
    const float* b2 = (const float*)d_in[8];
    const float* w3 = (const float*)d_in[9];
    const float* b3 = (const float*)d_in[10];
    const float* Cm = (const float*)d_in[11];
    float* out = (float*)d_out;

    wtrans_kernel<0><<<(256 * 258 + 255) / 256, 256>>>(w1);
    wtrans_kernel<1><<<(512 * 514 + 255) / 256, 256>>>(w2);
    wtrans_kernel<2><<<(1024 * 1026 + 255) / 256, 256>>>(w3);

    pool3_kernel<0><<<(BATCH * 256 * 64 * 64) / 256, 256>>>(p0);
    pool3_kernel<1><<<(BATCH * 512 * 32 * 32) / 256, 256>>>(p1);
    pool3_kernel<2><<<(BATCH * 1024 * 16 * 16) / 256, 256>>>(p2);

    conv1x1_kernel<0><<<dim3(256 / 64, 4096 / 64, BATCH), 256>>>(b1, out);
    conv1x1_kernel<1><<<dim3(512 / 64, 1024 / 64, BATCH), 256>>>(b2, out);
    conv1x1_kernel<2><<<dim3(1024 / 64, 256 / 64, BATCH), 256>>>(b3, out);

    resize_kernel<1><<<(BATCH * 512 * 4096) / 256, 256>>>(out);
    resize_kernel<2><<<(BATCH * 1024 * 4096) / 256, 256>>>(out);

    feats_kernel<<<BATCH * NPIX, 256>>>();
    cents_kernel<<<(NCENT + 255) / 256, 256>>>(Cm);

    dist_kernel<<<dim3(NCENT / 128, NPIX / 128, BATCH), 256>>>(Cm);

    select_kernel<<<BATCH * NPIX, 256>>>(out);
}

// round 3
// speedup vs baseline: 3.0689x; 3.0689x over previous
#include <cuda_runtime.h>
#include <cuda_bf16.h>
#include <cstdint>

#define BATCH 4
#define KDIM 1792
#define NPIX 4096
#define NCENT 4096
#define TOPK 200
#define PHI_OUT_C 896
#define SCORE_ELEMS (BATCH * TOPK * NPIX)

// dist GEMM tiling
#define TM 128
#define TN 128
#define KC 32
#define NCHUNK (KDIM / KC)   // 56
#define APAD 40              // padded row stride (elements): 20 words -> conflict-free frags

// ---------------- scratch (static device memory; no allocations) ----------------
__device__ float g_pool0[BATCH * 256 * 64 * 64];
__device__ float g_pool1[BATCH * 512 * 32 * 32];
__device__ float g_pool2[BATCH * 1024 * 16 * 16];
__device__ float g_conv1[BATCH * 512 * 32 * 32];
__device__ float g_conv2[BATCH * 1024 * 16 * 16];
__device__ float g_phi[(size_t)BATCH * NPIX * KDIM];           // (b, pix, k) fp32
__device__ __nv_bfloat16 g_phib[(size_t)BATCH * NPIX * KDIM];  // bf16 copy
__device__ __nv_bfloat16 g_Cb[(size_t)NCENT * KDIM];           // C^T bf16 (cent, k)
__device__ float g_feats[BATCH * NPIX];
__device__ float g_cents[NCENT];
__device__ float g_dist[(size_t)BATCH * NPIX * NCENT];
__device__ float g_wT1[258 * 256];
__device__ float g_wT2[514 * 512];
__device__ float g_wT3[1026 * 1024];

// ---------------- helpers ----------------
__device__ __forceinline__ uint32_t smem_u32(const void* p) {
    uint32_t a;
    asm("{ .reg .u64 t; cvta.to.shared.u64 t, %1; cvt.u32.u64 %0, t; }" : "=r"(a) : "l"(p));
    return a;
}
__device__ __forceinline__ void cpa16(uint32_t dst, const void* src) {
    asm volatile("cp.async.cg.shared.global [%0], [%1], 16;" ::"r"(dst), "l"(src));
}
__device__ __forceinline__ void mma_bf16(float* d, uint32_t a0, uint32_t a1, uint32_t a2,
                                         uint32_t a3, uint32_t b0, uint32_t b1) {
    asm volatile(
        "mma.sync.aligned.m16n8k16.row.col.f32.bf16.bf16.f32 "
        "{%0,%1,%2,%3}, {%4,%5,%6,%7}, {%8,%9}, {%0,%1,%2,%3};"
        : "+f"(d[0]), "+f"(d[1]), "+f"(d[2]), "+f"(d[3])
        : "r"(a0), "r"(a1), "r"(a2), "r"(a3), "r"(b0), "r"(b1));
}

// ---------------- level traits ----------------
template <int L> struct Lv {
    static constexpr int C = (L == 0) ? 256 : (L == 1) ? 512 : 1024;
    static constexpr int H = (L == 0) ? 64 : (L == 1) ? 32 : 16;
    static constexpr int PIX = H * H;
    static constexpr int CHOFF = (L == 0) ? 0 : (L == 1) ? 256 : 768;
};

// ---------------- 1) weight transpose ----------------
template <int L>
__global__ void wtrans_kernel(const float* __restrict__ w) {
    constexpr int CO = Lv<L>::C;
    constexpr int KI = CO + 2;
    float* wT = (L == 0) ? g_wT1 : (L == 1) ? g_wT2 : g_wT3;
    int i = blockIdx.x * blockDim.x + threadIdx.x;
    if (i >= CO * KI) return;
    int o = i / KI, k = i % KI;
    wT[k * CO + o] = w[i];
}

// ---------------- 2) avg_pool 3x3 /9 ----------------
template <int L>
__global__ void pool3_kernel(const float* __restrict__ x) {
    constexpr int C = Lv<L>::C, H = Lv<L>::H;
    float* y = (L == 0) ? g_pool0 : (L == 1) ? g_pool1 : g_pool2;
    int i = blockIdx.x * blockDim.x + threadIdx.x;
    constexpr int total = BATCH * C * H * H;
    if (i >= total) return;
    int w = i % H;
    int h = (i / H) % H;
    int bc = i / (H * H);
    const float* p = x + (size_t)bc * H * H;
    float s = 0.f;
#pragma unroll
    for (int dh = -1; dh <= 1; ++dh) {
        int hh = h + dh;
        if ((unsigned)hh < (unsigned)H) {
            const float* r = p + hh * H;
#pragma unroll
            for (int dw = -1; dw <= 1; ++dw) {
                int ww = w + dw;
                if ((unsigned)ww < (unsigned)H) s += r[ww];
            }
        }
    }
    y[i] = s * (1.0f / 9.0f);
}

// ---------------- 3) CoordConv 1x1 GEMM ----------------
template <int L>
__global__ __launch_bounds__(256) void conv1x1_kernel(const float* __restrict__ bias,
                                                      float* __restrict__ out) {
    constexpr int CI = Lv<L>::C, CO = CI, H = Lv<L>::H, PIX = Lv<L>::PIX;
    const float* pooled = (L == 0) ? g_pool0 : (L == 1) ? g_pool1 : g_pool2;
    const float* wT = (L == 0) ? g_wT1 : (L == 1) ? g_wT2 : g_wT3;
    float* convout = (L == 1) ? g_conv1 : g_conv2;

    int b = blockIdx.z;
    int oT = blockIdx.x * 64, pT = blockIdx.y * 64;
    __shared__ float As[16][64];
    __shared__ float Bs[16][64];
    int tid = threadIdx.x, tx = tid & 15, ty = tid >> 4;
    float acc[4][4] = {};
    const float* Ab = pooled + (size_t)b * CI * PIX;

    for (int kt = 0; kt < CI; kt += 16) {
        int lr = tid >> 4, lc = (tid & 15) * 4;
        *(float4*)&As[lr][lc] = *(const float4*)(Ab + (size_t)(kt + lr) * PIX + pT + lc);
        *(float4*)&Bs[lr][lc] = *(const float4*)(wT + (size_t)(kt + lr) * CO + oT + lc);
        __syncthreads();
#pragma unroll
        for (int k = 0; k < 16; k++) {
            float4 av = *(float4*)&As[k][ty * 4];
            float4 bv = *(float4*)&Bs[k][tx * 4];
            float a[4] = {av.x, av.y, av.z, av.w};
            float bb[4] = {bv.x, bv.y, bv.z, bv.w};
#pragma unroll
            for (int i2 = 0; i2 < 4; i2++)
#pragma unroll
                for (int j = 0; j < 4; j++) acc[i2][j] += a[i2] * bb[j];
        }
        __syncthreads();
    }

#pragma unroll
    for (int i2 = 0; i2 < 4; i2++) {
        int pix = pT + ty * 4 + i2;
        float xg = -1.0f + 2.0f * (float)(pix % H) / (float)(H - 1);
        float yg = -1.0f + 2.0f * (float)(pix / H) / (float)(H - 1);
#pragma unroll
        for (int j = 0; j < 4; j++) {
            int o = oT + tx * 4 + j;
            float v = acc[i2][j] + bias[o] + wT[(size_t)CI * CO + o] * xg +
                      wT[(size_t)(CI + 1) * CO + o] * yg;
            if (L == 0) {
                g_phi[((size_t)(b * NPIX) + pix) * KDIM + o] = v;
                out[SCORE_ELEMS + ((size_t)(b * PHI_OUT_C) + o) * NPIX + pix] = v;
            } else {
                convout[((size_t)(b * CO) + o) * PIX + pix] = v;
            }
        }
    }
}

// ---------------- 4) bilinear resize ----------------
template <int L>
__global__ void resize_kernel(float* __restrict__ out) {
    constexpr int C = Lv<L>::C, H = Lv<L>::H, CHOFF = Lv<L>::CHOFF;
    const float* conv = (L == 1) ? g_conv1 : g_conv2;
    int idx = blockIdx.x * blockDim.x + threadIdx.x;
    constexpr int total = BATCH * C * 4096;
    if (idx >= total) return;
    int opix = idx & 4095;
    int t = idx >> 12;
    int o = t % C;
    int b = t / C;
    int ox = opix & 63, oy = opix >> 6;
    constexpr float scale = (float)H / 64.0f;
    float u = fmaxf((ox + 0.5f) * scale - 0.5f, 0.0f);
    float v = fmaxf((oy + 0.5f) * scale - 0.5f, 0.0f);
    int x0 = min((int)u, H - 1), y0 = min((int)v, H - 1);
    int x1 = min(x0 + 1, H - 1), y1 = min(y0 + 1, H - 1);
    float fx = u - (float)x0, fy = v - (float)y0;
    const float* p = conv + ((size_t)(b * C) + o) * (H * H);
    float v00 = p[y0 * H + x0], v01 = p[y0 * H + x1];
    float v10 = p[y1 * H + x0], v11 = p[y1 * H + x1];
    float val = (1.f - fy) * ((1.f - fx) * v00 + fx * v01) + fy * ((1.f - fx) * v10 + fx * v11);
    g_phi[((size_t)(b * NPIX) + opix) * KDIM + CHOFF + o] = val;
    int gc = CHOFF + o;
    if (gc < PHI_OUT_C)
        out[SCORE_ELEMS + ((size_t)(b * PHI_OUT_C) + gc) * NPIX + opix] = val;
}

// ---------------- 5) converts + feats / cents ----------------
__global__ void phicvt_kernel() {
    size_t i = ((size_t)blockIdx.x * 256 + threadIdx.x) * 4;
    float4 v = *(const float4*)(g_phi + i);
    __nv_bfloat16 o[4] = {__float2bfloat16(v.x), __float2bfloat16(v.y),
                          __float2bfloat16(v.z), __float2bfloat16(v.w)};
    *(uint2*)(g_phib + i) = *(uint2*)o;
}

__global__ void ctrans_kernel(const float* __restrict__ Cm) {
    __shared__ float tile[32][33];
    int nb = blockIdx.x * 32, kb = blockIdx.y * 32;
    int tx = threadIdx.x, ty = threadIdx.y;
    for (int r = ty; r < 32; r += 8)
        tile[r][tx] = Cm[(size_t)(kb + r) * NCENT + nb + tx];
    __syncthreads();
    for (int r = ty; r < 32; r += 8)
        g_Cb[(size_t)(nb + r) * KDIM + kb + tx] = __float2bfloat16(tile[tx][r]);
}

__global__ void feats_kernel() {
    int row = blockIdx.x;
    const float* p = g_phi + (size_t)row * KDIM;
    float s = 0.f;
    for (int k = threadIdx.x; k < KDIM; k += 256) {
        float v = p[k];
        s += v * v;
    }
    __shared__ float sh[256];
    sh[threadIdx.x] = s;
    __syncthreads();
    for (int off = 128; off > 0; off >>= 1) {
        if (threadIdx.x < off) sh[threadIdx.x] += sh[threadIdx.x + off];
        __syncthreads();
    }
    if (threadIdx.x == 0) g_feats[row] = sh[0];
}

__global__ void cents_kernel(const float* __restrict__ Cm) {
    int j = blockIdx.x * blockDim.x + threadIdx.x;
    if (j >= NCENT) return;
    float s = 0.f;
    for (int k = 0; k < KDIM; k++) {
        float v = Cm[(size_t)k * NCENT + j];
        s += v * v;
    }
    g_cents[j] = s;
}

// ---------------- 6) distance GEMM via mma.sync bf16 ----------------
// CTA 128x128, 8 warps (4m x 2n), warp tile 32x64, K-chunk 32, cp.async double buffer.
__global__ __launch_bounds__(256, 2) void dist_mma_kernel() {
    __shared__ __nv_bfloat16 As[2][TM * APAD];
    __shared__ __nv_bfloat16 Bs[2][TN * APAD];

    int tid = threadIdx.x;
    int wid = tid >> 5, lane = tid & 31;
    int wm = wid & 3, wn = wid >> 2;           // warp position: 4 x 2
    int g = lane >> 2, c2 = (lane & 3) * 2;    // fragment row group / col pair
    int b = blockIdx.z;
    int iT = blockIdx.y * TM;
    int jT = blockIdx.x * TN;

    const char* Abase = (const char*)(g_phib + (size_t)(b * NPIX + iT) * KDIM);
    const char* Bbase = (const char*)(g_Cb + (size_t)jT * KDIM);
    uint32_t sA[2] = {smem_u32(&As[0][0]), smem_u32(&As[1][0])};
    uint32_t sB[2] = {smem_u32(&Bs[0][0]), smem_u32(&Bs[1][0])};

    int r0 = tid >> 2, c0 = tid & 3;           // chunk-load coords (q=0)
    int r1 = (tid + 256) >> 2, c1 = tid & 3;   // q=1

    float acc[2][8][4];
#pragma unroll
    for (int mt = 0; mt < 2; mt++)
#pragma unroll
        for (int nt = 0; nt < 8; nt++)
#pragma unroll
            for (int q = 0; q < 4; q++) acc[mt][nt][q] = 0.0f;

#define ISSUE_CHUNK(i, buf)                                                               \
    do {                                                                                  \
        cpa16(sA[buf] + (uint32_t)(r0 * APAD + c0 * 8) * 2,                               \
              Abase + ((size_t)r0 * KDIM + (i) * KC + c0 * 8) * 2);                       \
        cpa16(sA[buf] + (uint32_t)(r1 * APAD + c1 * 8) * 2,                               \
              Abase + ((size_t)r1 * KDIM + (i) * KC + c1 * 8) * 2);                       \
        cpa16(sB[buf] + (uint32_t)(r0 * APAD + c0 * 8) * 2,                               \
              Bbase + ((size_t)r0 * KDIM + (i) * KC + c0 * 8) * 2);                       \
        cpa16(sB[buf] + (uint32_t)(r1 * APAD + c1 * 8) * 2,                               \
              Bbase + ((size_t)r1 * KDIM + (i) * KC + c1 * 8) * 2);                       \
        asm volatile("cp.async.commit_group;");                                           \
    } while (0)

    ISSUE_CHUNK(0, 0);

    for (int i = 0; i < NCHUNK; i++) {
        int buf = i & 1;
        if (i + 1 < NCHUNK) {
            ISSUE_CHUNK(i + 1, (i + 1) & 1);
            asm volatile("cp.async.wait_group 1;");
        } else {
            asm volatile("cp.async.wait_group 0;");
        }
        __syncthreads();

        const __nv_bfloat16* Ab = &As[buf][0];
        const __nv_bfloat16* Bb = &Bs[buf][0];
#pragma unroll
        for (int ks = 0; ks < 2; ks++) {
            int k0 = ks * 16;
            uint32_t bf[8][2];
#pragma unroll
            for (int nt = 0; nt < 8; nt++) {
                int n = wn * 64 + nt * 8 + g;
                bf[nt][0] = *(const uint32_t*)&Bb[n * APAD + k0 + c2];
                bf[nt][1] = *(const uint32_t*)&Bb[n * APAD + k0 + c2 + 8];
            }
#pragma unroll
            for (int mt = 0; mt < 2; mt++) {
                int m = wm * 32 + mt * 16 + g;
                uint32_t a0 = *(const uint32_t*)&Ab[m * APAD + k0 + c2];
                uint32_t a1 = *(const uint32_t*)&Ab[(m + 8) * APAD + k0 + c2];
                uint32_t a2 = *(const uint32_t*)&Ab[m * APAD + k0 + c2 + 8];
                uint32_t a3 = *(const uint32_t*)&Ab[(m + 8) * APAD + k0 + c2 + 8];
#pragma unroll
                for (int nt = 0; nt < 8; nt++)
                    mma_bf16(acc[mt][nt], a0, a1, a2, a3, bf[nt][0], bf[nt][1]);
            }
        }
        __syncthreads();
    }
#undef ISSUE_CHUNK

    // epilogue: dist = sqrt(feats + cents - 2*dot)
#pragma unroll
    for (int mt = 0; mt < 2; mt++) {
        int gr = iT + wm * 32 + mt * 16 + g;
        float f0 = g_feats[b * NPIX + gr];
        float f1 = g_feats[b * NPIX + gr + 8];
        float* row0 = g_dist + (size_t)(b * NPIX + gr) * NCENT;
        float* row1 = g_dist + (size_t)(b * NPIX + gr + 8) * NCENT;
#pragma unroll
        for (int nt = 0; nt < 8; nt++) {
            int gc = jT + wn * 64 + nt * 8 + c2;
            float ce0 = __ldg(&g_cents[gc]);
            float ce1 = __ldg(&g_cents[gc + 1]);
            float2 v0, v1;
            v0.x = sqrtf(fmaxf(f0 + ce0 - 2.0f * acc[mt][nt][0], 0.0f));
            v0.y = sqrtf(fmaxf(f0 + ce1 - 2.0f * acc[mt][nt][1], 0.0f));
            v1.x = sqrtf(fmaxf(f1 + ce0 - 2.0f * acc[mt][nt][2], 0.0f));
            v1.y = sqrtf(fmaxf(f1 + ce1 - 2.0f * acc[mt][nt][3], 0.0f));
            *(float2*)(row0 + gc) = v0;
            *(float2*)(row1 + gc) = v1;
        }
    }
}

// ---------------- 7) top-200 per row ----------------
__global__ __launch_bounds__(256) void select_kernel(float* __restrict__ out) {
    int row = blockIdx.x;
    int b = row >> 12;
    int pix = row & 4095;
    const float* d = g_dist + (size_t)row * NCENT;
    int t = threadIdx.x;

    unsigned key[16];
#pragma unroll
    for (int j = 0; j < 16; j++) key[j] = __float_as_uint(d[t + j * 256]);

    unsigned mn = 0xFFFFFFFFu, mx = 0u;
#pragma unroll
    for (int j = 0; j < 16; j++) {
        mn = min(mn, key[j]);
        mx = max(mx, key[j]);
    }
    for (int off = 16; off; off >>= 1) {
        mn = min(mn, __shfl_down_sync(0xFFFFFFFFu, mn, off));
        mx = max(mx, __shfl_down_sync(0xFFFFFFFFu, mx, off));
    }
    __shared__ unsigned shmn[8], shmx[8];
    __shared__ unsigned s_lo, s_hi;
    if ((t & 31) == 0) {
        shmn[t >> 5] = mn;
        shmx[t >> 5] = mx;
    }
    __syncthreads();
    if (t == 0) {
        unsigned a = shmn[0], z = shmx[0];
        for (int w = 1; w < 8; w++) {
            a = min(a, shmn[w]);
            z = max(z, shmx[w]);
        }
        s_lo = a;
        s_hi = z;
    }
    __syncthreads();
    unsigned lo = s_lo, hi = s_hi;

    __shared__ int shcnt[8];
    __shared__ int sh_total;
    while (lo < hi) {
        unsigned mid = lo + ((hi - lo) >> 1);
        int c = 0;
#pragma unroll
        for (int j = 0; j < 16; j++) c += (key[j] <= mid) ? 1 : 0;
        for (int off = 16; off; off >>= 1) c += __shfl_down_sync(0xFFFFFFFFu, c, off);
        if ((t & 31) == 0) shcnt[t >> 5] = c;
        __syncthreads();
        if (t == 0) {
            int s = 0;
            for (int w = 0; w < 8; w++) s += shcnt[w];
            sh_total = s;
        }
        __syncthreads();
        int total = sh_total;
        __syncthreads();
        if (total >= TOPK)
            hi = mid;
        else
            lo = mid + 1;
    }
    unsigned T = lo;

    __shared__ unsigned cand[256];
    __shared__ int s_cnt;
    cand[t] = T;
    if (t == 0) s_cnt = 0;
    __syncthreads();
#pragma unroll
    for (int j = 0; j < 16; j++) {
        if (key[j] < T) {
            int p = atomicAdd(&s_cnt, 1);
            if (p < 256) cand[p] = key[j];
        }
    }
    __syncthreads();

    for (int k = 2; k <= 256; k <<= 1) {
        for (int j = k >> 1; j > 0; j >>= 1) {
            int ixj = t ^ j;
            if (ixj > t) {
                unsigned a = cand[t], z = cand[ixj];
                bool up = ((t & k) == 0);
                if ((a > z) == up) {
                    cand[t] = z;
                    cand[ixj] = a;
                }
            }
            __syncthreads();
        }
    }

    if (t < TOPK)
        out[((size_t)(b * TOPK) + t) * NPIX + pix] = __uint_as_float(cand[t]);
}

// ---------------- launch ----------------
extern "C" void kernel_launch(void* const* d_in, const int* in_sizes, int n_in,
                              void* d_out, int out_size) {
    const float* p0 = (const float*)d_in[0];
    const float* p1 = (const float*)d_in[1];
    const float* p2 = (const float*)d_in[2];
    const float* w1 = (const float*)d_in[5];
    const float* b1 = (const float*)d_in[6];
    const float* w2 = (const float*)d_in[7];
    const float* b2 = (const float*)d_in[8];
    const float* w3 = (const float*)d_in[9];
    const float* b3 = (const float*)d_in[10];
    const float* Cm = (const float*)d_in[11];
    float* out = (float*)d_out;

    wtrans_kernel<0><<<(256 * 258 + 255) / 256, 256>>>(w1);
    wtrans_kernel<1><<<(512 * 514 + 255) / 256, 256>>>(w2);
    wtrans_kernel<2><<<(1024 * 1026 + 255) / 256, 256>>>(w3);

    pool3_kernel<0><<<(BATCH * 256 * 64 * 64) / 256, 256>>>(p0);
    pool3_kernel<1><<<(BATCH * 512 * 32 * 32) / 256, 256>>>(p1);
    pool3_kernel<2><<<(BATCH * 1024 * 16 * 16) / 256, 256>>>(p2);

    conv1x1_kernel<0><<<dim3(256 / 64, 4096 / 64, BATCH), 256>>>(b1, out);
    conv1x1_kernel<1><<<dim3(512 / 64, 1024 / 64, BATCH), 256>>>(b2, out);
    conv1x1_kernel<2><<<dim3(1024 / 64, 256 / 64, BATCH), 256>>>(b3, out);

    resize_kernel<1><<<(BATCH * 512 * 4096) / 256, 256>>>(out);
    resize_kernel<2><<<(BATCH * 1024 * 4096) / 256, 256>>>(out);

    ctrans_kernel<<<dim3(NCENT / 32, KDIM / 32), dim3(32, 8)>>>(Cm);
    phicvt_kernel<<<(int)(((size_t)BATCH * NPIX * KDIM / 4) / 256), 256>>>();

    feats_kernel<<<BATCH * NPIX, 256>>>();
    cents_kernel<<<(NCENT + 255) / 256, 256>>>(Cm);

    dist_mma_kernel<<<dim3(NCENT / TN, NPIX / TM, BATCH), 256>>>();

    select_kernel<<<BATCH * NPIX, 256>>>(out);
}

// round 4
// speedup vs baseline: 3.8058x; 1.2401x over previous
#include <cuda_runtime.h>
#include <cuda_bf16.h>
#include <cstdint>

#define BATCH 4
#define KDIM 1792
#define NPIX 4096
#define NCENT 4096
#define TOPK 200
#define PHI_OUT_C 896
#define SCORE_ELEMS (BATCH * TOPK * NPIX)

// dist GEMM tiling
#define TM 128
#define TN 128
#define KC 64
#define NCHUNK (KDIM / KC)  // 28
#define ROWB 144            // bytes per smem row (64 bf16 + 8 pad)
#define STG 36864           // bytes per stage: (128+128) rows * 144
#define DIST_SMEM (2 * STG) // 73728

// ---------------- scratch (static device memory; no allocations) ----------------
__device__ float g_pool0[BATCH * 256 * 64 * 64];
__device__ float g_pool1[BATCH * 512 * 32 * 32];
__device__ float g_pool2[BATCH * 1024 * 16 * 16];
__device__ float g_conv1[BATCH * 512 * 32 * 32];   // pixel-major [b][pix][o]
__device__ float g_conv2[BATCH * 1024 * 16 * 16];  // pixel-major
__device__ __nv_bfloat16 g_phib[(size_t)BATCH * NPIX * KDIM];  // (b, pix, k)
__device__ __nv_bfloat16 g_Cb[(size_t)NCENT * KDIM];           // C^T (cent, k)
__device__ float g_feats[BATCH * NPIX];
__device__ float g_cents[NCENT];
__device__ float g_dist[(size_t)BATCH * NPIX * NCENT];
__device__ float g_wT1[258 * 256];
__device__ float g_wT2[514 * 512];
__device__ float g_wT3[1026 * 1024];

// ---------------- helpers ----------------
__device__ __forceinline__ uint32_t smem_u32(const void* p) {
    uint32_t a;
    asm("{ .reg .u64 t; cvta.to.shared.u64 t, %1; cvt.u32.u64 %0, t; }" : "=r"(a) : "l"(p));
    return a;
}
__device__ __forceinline__ void cpa16(uint32_t dst, const void* src) {
    asm volatile("cp.async.cg.shared.global [%0], [%1], 16;" ::"r"(dst), "l"(src));
}
__device__ __forceinline__ void ldsm4(uint32_t& r0, uint32_t& r1, uint32_t& r2, uint32_t& r3,
                                      uint32_t a) {
    asm volatile("ldmatrix.sync.aligned.m8n8.x4.shared.b16 {%0,%1,%2,%3}, [%4];"
                 : "=r"(r0), "=r"(r1), "=r"(r2), "=r"(r3)
                 : "r"(a));
}
__device__ __forceinline__ void mma_bf16(float* d, uint32_t a0, uint32_t a1, uint32_t a2,
                                         uint32_t a3, uint32_t b0, uint32_t b1) {
    asm volatile(
        "mma.sync.aligned.m16n8k16.row.col.f32.bf16.bf16.f32 "
        "{%0,%1,%2,%3}, {%4,%5,%6,%7}, {%8,%9}, {%0,%1,%2,%3};"
        : "+f"(d[0]), "+f"(d[1]), "+f"(d[2]), "+f"(d[3])
        : "r"(a0), "r"(a1), "r"(a2), "r"(a3), "r"(b0), "r"(b1));
}

// ---------------- level traits ----------------
template <int L> struct Lv {
    static constexpr int C = (L == 0) ? 256 : (L == 1) ? 512 : 1024;
    static constexpr int H = (L == 0) ? 64 : (L == 1) ? 32 : 16;
    static constexpr int PIX = H * H;
    static constexpr int CHOFF = (L == 0) ? 0 : (L == 1) ? 256 : 768;
};

// ---------------- 1) weight transpose ----------------
template <int L>
__global__ void wtrans_kernel(const float* __restrict__ w) {
    constexpr int CO = Lv<L>::C;
    constexpr int KI = CO + 2;
    float* wT = (L == 0) ? g_wT1 : (L == 1) ? g_wT2 : g_wT3;
    int i = blockIdx.x * blockDim.x + threadIdx.x;
    if (i >= CO * KI) return;
    int o = i / KI, k = i % KI;
    wT[k * CO + o] = w[i];
}

// ---------------- 2) avg_pool 3x3 /9 ----------------
template <int L>
__global__ void pool3_kernel(const float* __restrict__ x) {
    constexpr int C = Lv<L>::C, H = Lv<L>::H;
    float* y = (L == 0) ? g_pool0 : (L == 1) ? g_pool1 : g_pool2;
    int i = blockIdx.x * blockDim.x + threadIdx.x;
    constexpr int total = BATCH * C * H * H;
    if (i >= total) return;
    int w = i % H;
    int h = (i / H) % H;
    int bc = i / (H * H);
    const float* p = x + (size_t)bc * H * H;
    float s = 0.f;
#pragma unroll
    for (int dh = -1; dh <= 1; ++dh) {
        int hh = h + dh;
        if ((unsigned)hh < (unsigned)H) {
            const float* r = p + hh * H;
#pragma unroll
            for (int dw = -1; dw <= 1; ++dw) {
                int ww = w + dw;
                if ((unsigned)ww < (unsigned)H) s += r[ww];
            }
        }
    }
    y[i] = s * (1.0f / 9.0f);
}

// ---------------- 3) CoordConv 1x1 GEMM ----------------
// L0 writes bf16 phi (k-contiguous) + fp32 out slice; L1/L2 write pixel-major conv.
template <int L>
__global__ __launch_bounds__(256) void conv1x1_kernel(const float* __restrict__ bias,
                                                      float* __restrict__ out) {
    constexpr int CI = Lv<L>::C, CO = CI, H = Lv<L>::H, PIX = Lv<L>::PIX;
    const float* pooled = (L == 0) ? g_pool0 : (L == 1) ? g_pool1 : g_pool2;
    const float* wT = (L == 0) ? g_wT1 : (L == 1) ? g_wT2 : g_wT3;
    float* convout = (L == 1) ? g_conv1 : g_conv2;

    int b = blockIdx.z;
    int oT = blockIdx.x * 64, pT = blockIdx.y * 64;
    __shared__ float As[16][64];
    __shared__ float Bs[16][64];
    int tid = threadIdx.x, tx = tid & 15, ty = tid >> 4;
    float acc[4][4] = {};
    const float* Ab = pooled + (size_t)b * CI * PIX;

    for (int kt = 0; kt < CI; kt += 16) {
        int lr = tid >> 4, lc = (tid & 15) * 4;
        *(float4*)&As[lr][lc] = *(const float4*)(Ab + (size_t)(kt + lr) * PIX + pT + lc);
        *(float4*)&Bs[lr][lc] = *(const float4*)(wT + (size_t)(kt + lr) * CO + oT + lc);
        __syncthreads();
#pragma unroll
        for (int k = 0; k < 16; k++) {
            float4 av = *(float4*)&As[k][ty * 4];
            float4 bv = *(float4*)&Bs[k][tx * 4];
            float a[4] = {av.x, av.y, av.z, av.w};
            float bb[4] = {bv.x, bv.y, bv.z, bv.w};
#pragma unroll
            for (int i2 = 0; i2 < 4; i2++)
#pragma unroll
                for (int j = 0; j < 4; j++) acc[i2][j] += a[i2] * bb[j];
        }
        __syncthreads();
    }

#pragma unroll
    for (int i2 = 0; i2 < 4; i2++) {
        int pix = pT + ty * 4 + i2;
        float xg = -1.0f + 2.0f * (float)(pix % H) / (float)(H - 1);
        float yg = -1.0f + 2.0f * (float)(pix / H) / (float)(H - 1);
        float v[4];
#pragma unroll
        for (int j = 0; j < 4; j++) {
            int o = oT + tx * 4 + j;
            v[j] = acc[i2][j] + bias[o] + wT[(size_t)CI * CO + o] * xg +
                   wT[(size_t)(CI + 1) * CO + o] * yg;
        }
        int o0 = oT + tx * 4;
        if (L == 0) {
            __nv_bfloat16 hv[4] = {__float2bfloat16(v[0]), __float2bfloat16(v[1]),
                                   __float2bfloat16(v[2]), __float2bfloat16(v[3])};
            *(uint2*)&g_phib[((size_t)(b * NPIX) + pix) * KDIM + o0] = *(uint2*)hv;
#pragma unroll
            for (int j = 0; j < 4; j++)
                out[SCORE_ELEMS + ((size_t)(b * PHI_OUT_C) + o0 + j) * NPIX + pix] = v[j];
        } else {
            *(float4*)&convout[((size_t)(b * PIX) + pix) * CO + o0] = *(float4*)v;
        }
    }
}

// ---------------- 4) bilinear resize, o-fastest (coalesced) ----------------
template <int L>
__global__ void resize_kernel(float* __restrict__ out) {
    constexpr int C = Lv<L>::C, H = Lv<L>::H, CHOFF = Lv<L>::CHOFF, PIX = Lv<L>::PIX;
    const float* conv = (L == 1) ? g_conv1 : g_conv2;
    int idx = blockIdx.x * blockDim.x + threadIdx.x;
    constexpr int total = BATCH * C * 4096 / 2;
    if (idx >= total) return;
    int o2 = (idx & (C / 2 - 1)) * 2;
    int rest = idx / (C / 2);
    int opix = rest & 4095;
    int b = rest >> 12;
    int ox = opix & 63, oy = opix >> 6;
    constexpr float scale = (float)H / 64.0f;
    float u = fmaxf((ox + 0.5f) * scale - 0.5f, 0.0f);
    float v = fmaxf((oy + 0.5f) * scale - 0.5f, 0.0f);
    int x0 = min((int)u, H - 1), y0 = min((int)v, H - 1);
    int x1 = min(x0 + 1, H - 1), y1 = min(y0 + 1, H - 1);
    float fx = u - (float)x0, fy = v - (float)y0;
    const float* p = conv + (size_t)(b * PIX) * C;
    float2 v00 = *(const float2*)&p[(size_t)(y0 * H + x0) * C + o2];
    float2 v01 = *(const float2*)&p[(size_t)(y0 * H + x1) * C + o2];
    float2 v10 = *(const float2*)&p[(size_t)(y1 * H + x0) * C + o2];
    float2 v11 = *(const float2*)&p[(size_t)(y1 * H + x1) * C + o2];
    float w00 = (1.f - fy) * (1.f - fx), w01 = (1.f - fy) * fx;
    float w10 = fy * (1.f - fx), w11 = fy * fx;
    float val0 = w00 * v00.x + w01 * v01.x + w10 * v10.x + w11 * v11.x;
    float val1 = w00 * v00.y + w01 * v01.y + w10 * v10.y + w11 * v11.y;
    __nv_bfloat16 hv[2] = {__float2bfloat16(val0), __float2bfloat16(val1)};
    *(uint32_t*)&g_phib[((size_t)(b * NPIX) + opix) * KDIM + CHOFF + o2] = *(uint32_t*)hv;
    int gc = CHOFF + o2;
    if (gc < PHI_OUT_C) {
        out[SCORE_ELEMS + ((size_t)(b * PHI_OUT_C) + gc) * NPIX + opix] = val0;
        out[SCORE_ELEMS + ((size_t)(b * PHI_OUT_C) + gc + 1) * NPIX + opix] = val1;
    }
}

// ---------------- 5) C transpose + feats / cents ----------------
__global__ void ctrans_kernel(const float* __restrict__ Cm) {
    __shared__ float tile[32][33];
    int nb = blockIdx.x * 32, kb = blockIdx.y * 32;
    int tx = threadIdx.x, ty = threadIdx.y;
    for (int r = ty; r < 32; r += 8)
        tile[r][tx] = Cm[(size_t)(kb + r) * NCENT + nb + tx];
    __syncthreads();
    for (int r = ty; r < 32; r += 8)
        g_Cb[(size_t)(nb + r) * KDIM + kb + tx] = __float2bfloat16(tile[tx][r]);
}

__global__ void feats_kernel() {
    int row = blockIdx.x;
    const __nv_bfloat16* p = g_phib + (size_t)row * KDIM;
    float s = 0.f;
    for (int k = threadIdx.x; k < KDIM; k += 256) {
        float v = __bfloat162float(p[k]);
        s += v * v;
    }
    __shared__ float sh[256];
    sh[threadIdx.x] = s;
    __syncthreads();
    for (int off = 128; off > 0; off >>= 1) {
        if (threadIdx.x < off) sh[threadIdx.x] += sh[threadIdx.x + off];
        __syncthreads();
    }
    if (threadIdx.x == 0) g_feats[row] = sh[0];
}

__global__ void cents_kernel(const float* __restrict__ Cm) {
    int j = blockIdx.x * blockDim.x + threadIdx.x;
    if (j >= NCENT) return;
    float s = 0.f;
    for (int k = 0; k < KDIM; k++) {
        float v = Cm[(size_t)k * NCENT + j];
        s += v * v;
    }
    g_cents[j] = s;
}

// ---------------- 6) distance GEMM: ldmatrix + mma.sync, KC=64, 2-stage ----------------
__global__ __launch_bounds__(256, 2) void dist_mma_kernel() {
    extern __shared__ char ds[];
    uint32_t sbase = smem_u32(ds);

    int tid = threadIdx.x, wid = tid >> 5, lane = tid & 31;
    int wm = wid & 3, wn = wid >> 2;
    int b = blockIdx.z;
    int iT = blockIdx.y * TM;
    int jT = blockIdx.x * TN;

    const char* Abase = (const char*)(g_phib + (size_t)(b * NPIX + iT) * KDIM);
    const char* Bbase = (const char*)(g_Cb + (size_t)jT * KDIM);

    // cp.async coords: chunk = tid + q*256 -> row = chunk>>3 = crow + q*32, c = tid&7
    int crow = tid >> 3;
    int cc = tid & 7;

    // ldmatrix per-lane offsets
    int sub = lane >> 3, r8 = lane & 7;
    uint32_t aoff[2], boff[4];
#pragma unroll
    for (int mt = 0; mt < 2; mt++)
        aoff[mt] = (uint32_t)((wm * 32 + mt * 16 + (sub & 1) * 8 + r8) * ROWB + (sub >> 1) * 16);
#pragma unroll
    for (int nt2 = 0; nt2 < 4; nt2++)
        boff[nt2] = (uint32_t)((wn * 64 + nt2 * 16 + (sub >> 1) * 8 + r8) * ROWB + (sub & 1) * 16);

    float acc[2][8][4];
#pragma unroll
    for (int mt = 0; mt < 2; mt++)
#pragma unroll
        for (int nt = 0; nt < 8; nt++)
#pragma unroll
            for (int q = 0; q < 4; q++) acc[mt][nt][q] = 0.0f;

#define ISSUE_CHUNK(i, buf)                                                                \
    do {                                                                                   \
        uint32_t ab_ = sbase + (buf) * STG;                                                \
        uint32_t bb_ = ab_ + 18432;                                                        \
        _Pragma("unroll") for (int q = 0; q < 4; q++) {                                    \
            int row = crow + q * 32;                                                       \
            cpa16(ab_ + row * ROWB + cc * 16,                                              \
                  Abase + ((size_t)row * KDIM + (size_t)(i) * KC + cc * 8) * 2);           \
            cpa16(bb_ + row * ROWB + cc * 16,                                              \
                  Bbase + ((size_t)row * KDIM + (size_t)(i) * KC + cc * 8) * 2);           \
        }                                                                                  \
        asm volatile("cp.async.commit_group;");                                            \
    } while (0)

    ISSUE_CHUNK(0, 0);

    for (int i = 0; i < NCHUNK; i++) {
        int buf = i & 1;
        if (i + 1 < NCHUNK) {
            ISSUE_CHUNK(i + 1, (i + 1) & 1);
            asm volatile("cp.async.wait_group 1;");
        } else {
            asm volatile("cp.async.wait_group 0;");
        }
        __syncthreads();

        uint32_t ab = sbase + buf * STG;
        uint32_t bb = ab + 18432;
#pragma unroll
        for (int ks = 0; ks < 4; ks++) {
            uint32_t bf[8][2];
#pragma unroll
            for (int nt2 = 0; nt2 < 4; nt2++)
                ldsm4(bf[nt2 * 2][0], bf[nt2 * 2][1], bf[nt2 * 2 + 1][0], bf[nt2 * 2 + 1][1],
                      bb + boff[nt2] + ks * 32);
#pragma unroll
            for (int mt = 0; mt < 2; mt++) {
                uint32_t a0, a1, a2, a3;
                ldsm4(a0, a1, a2, a3, ab + aoff[mt] + ks * 32);
#pragma unroll
                for (int nt = 0; nt < 8; nt++)
                    mma_bf16(acc[mt][nt], a0, a1, a2, a3, bf[nt][0], bf[nt][1]);
            }
        }
        __syncthreads();
    }
#undef ISSUE_CHUNK

    // epilogue: dist = sqrt(feats + cents - 2*dot)
    int g = lane >> 2, c2 = (lane & 3) * 2;
#pragma unroll
    for (int mt = 0; mt < 2; mt++) {
        int gr = iT + wm * 32 + mt * 16 + g;
        float f0 = g_feats[b * NPIX + gr];
        float f1 = g_feats[b * NPIX + gr + 8];
        float* row0 = g_dist + (size_t)(b * NPIX + gr) * NCENT;
        float* row1 = g_dist + (size_t)(b * NPIX + gr + 8) * NCENT;
#pragma unroll
        for (int nt = 0; nt < 8; nt++) {
            int gc = jT + wn * 64 + nt * 8 + c2;
            float ce0 = __ldg(&g_cents[gc]);
            float ce1 = __ldg(&g_cents[gc + 1]);
            float2 v0, v1;
            v0.x = sqrtf(fmaxf(f0 + ce0 - 2.0f * acc[mt][nt][0], 0.0f));
            v0.y = sqrtf(fmaxf(f0 + ce1 - 2.0f * acc[mt][nt][1], 0.0f));
            v1.x = sqrtf(fmaxf(f1 + ce0 - 2.0f * acc[mt][nt][2], 0.0f));
            v1.y = sqrtf(fmaxf(f1 + ce1 - 2.0f * acc[mt][nt][3], 0.0f));
            *(float2*)(row0 + gc) = v0;
            *(float2*)(row1 + gc) = v1;
        }
    }
}

// ---------------- 7) top-200 per row ----------------
__global__ __launch_bounds__(256) void select_kernel(float* __restrict__ out) {
    int row = blockIdx.x;
    int b = row >> 12;
    int pix = row & 4095;
    const float* d = g_dist + (size_t)row * NCENT;
    int t = threadIdx.x;

    unsigned key[16];
#pragma unroll
    for (int j = 0; j < 16; j++) key[j] = __float_as_uint(d[t + j * 256]);

    unsigned mn = 0xFFFFFFFFu, mx = 0u;
#pragma unroll
    for (int j = 0; j < 16; j++) {
        mn = min(mn, key[j]);
        mx = max(mx, key[j]);
    }
    for (int off = 16; off; off >>= 1) {
        mn = min(mn, __shfl_down_sync(0xFFFFFFFFu, mn, off));
        mx = max(mx, __shfl_down_sync(0xFFFFFFFFu, mx, off));
    }
    __shared__ unsigned shmn[8], shmx[8];
    __shared__ unsigned s_lo, s_hi;
    if ((t & 31) == 0) {
        shmn[t >> 5] = mn;
        shmx[t >> 5] = mx;
    }
    __syncthreads();
    if (t == 0) {
        unsigned a = shmn[0], z = shmx[0];
        for (int w = 1; w < 8; w++) {
            a = min(a, shmn[w]);
            z = max(z, shmx[w]);
        }
        s_lo = a;
        s_hi = z;
    }
    __syncthreads();
    unsigned lo = s_lo, hi = s_hi;

    __shared__ int shcnt[8];
    __shared__ int sh_total;
    while (lo < hi) {
        unsigned mid = lo + ((hi - lo) >> 1);
        int c = 0;
#pragma unroll
        for (int j = 0; j < 16; j++) c += (key[j] <= mid) ? 1 : 0;
        for (int off = 16; off; off >>= 1) c += __shfl_down_sync(0xFFFFFFFFu, c, off);
        if ((t & 31) == 0) shcnt[t >> 5] = c;
        __syncthreads();
        if (t == 0) {
            int s = 0;
            for (int w = 0; w < 8; w++) s += shcnt[w];
            sh_total = s;
        }
        __syncthreads();
        int total = sh_total;
        __syncthreads();
        if (total >= TOPK)
            hi = mid;
        else
            lo = mid + 1;
    }
    unsigned T = lo;

    __shared__ unsigned cand[256];
    __shared__ int s_cnt;
    cand[t] = T;
    if (t == 0) s_cnt = 0;
    __syncthreads();
#pragma unroll
    for (int j = 0; j < 16; j++) {
        if (key[j] < T) {
            int p = atomicAdd(&s_cnt, 1);
            if (p < 256) cand[p] = key[j];
        }
    }
    __syncthreads();

    for (int k = 2; k <= 256; k <<= 1) {
        for (int j = k >> 1; j > 0; j >>= 1) {
            int ixj = t ^ j;
            if (ixj > t) {
                unsigned a = cand[t], z = cand[ixj];
                bool up = ((t & k) == 0);
                if ((a > z) == up) {
                    cand[t] = z;
                    cand[ixj] = a;
                }
            }
            __syncthreads();
        }
    }

    if (t < TOPK)
        out[((size_t)(b * TOPK) + t) * NPIX + pix] = __uint_as_float(cand[t]);
}

// ---------------- launch ----------------
extern "C" void kernel_launch(void* const* d_in, const int* in_sizes, int n_in,
                              void* d_out, int out_size) {
    const float* p0 = (const float*)d_in[0];
    const float* p1 = (const float*)d_in[1];
    const float* p2 = (const float*)d_in[2];
    const float* w1 = (const float*)d_in[5];
    const float* b1 = (const float*)d_in[6];
    const float* w2 = (const float*)d_in[7];
    const float* b2 = (const float*)d_in[8];
    const float* w3 = (const float*)d_in[9];
    const float* b3 = (const float*)d_in[10];
    const float* Cm = (const float*)d_in[11];
    float* out = (float*)d_out;

    cudaFuncSetAttribute(dist_mma_kernel, cudaFuncAttributeMaxDynamicSharedMemorySize,
                         DIST_SMEM);

    wtrans_kernel<0><<<(256 * 258 + 255) / 256, 256>>>(w1);
    wtrans_kernel<1><<<(512 * 514 + 255) / 256, 256>>>(w2);
    wtrans_kernel<2><<<(1024 * 1026 + 255) / 256, 256>>>(w3);

    pool3_kernel<0><<<(BATCH * 256 * 64 * 64) / 256, 256>>>(p0);
    pool3_kernel<1><<<(BATCH * 512 * 32 * 32) / 256, 256>>>(p1);
    pool3_kernel<2><<<(BATCH * 1024 * 16 * 16) / 256, 256>>>(p2);

    conv1x1_kernel<0><<<dim3(256 / 64, 4096 / 64, BATCH), 256>>>(b1, out);
    conv1x1_kernel<1><<<dim3(512 / 64, 1024 / 64, BATCH), 256>>>(b2, out);
    conv1x1_kernel<2><<<dim3(1024 / 64, 256 / 64, BATCH), 256>>>(b3, out);

    resize_kernel<1><<<(BATCH * 512 * 4096 / 2 + 255) / 256, 256>>>(out);
    resize_kernel<2><<<(BATCH * 1024 * 4096 / 2 + 255) / 256, 256>>>(out);

    ctrans_kernel<<<dim3(NCENT / 32, KDIM / 32), dim3(32, 8)>>>(Cm);

    feats_kernel<<<BATCH * NPIX, 256>>>();
    cents_kernel<<<(NCENT + 255) / 256, 256>>>(Cm);

    dist_mma_kernel<<<dim3(NCENT / TN, NPIX / TM, BATCH), 256, DIST_SMEM>>>();

    select_kernel<<<BATCH * NPIX, 256>>>(out);
}

// round 5
// speedup vs baseline: 3.9618x; 1.0410x over previous
#include <cuda_runtime.h>
#include <cuda_bf16.h>
#include <cstdint>

#define BATCH 4
#define KDIM 1792
#define NPIX 4096
#define NCENT 4096
#define TOPK 200
#define PHI_OUT_C 896
#define SCORE_ELEMS (BATCH * TOPK * NPIX)

// dist GEMM tiling: 128(pix) x 256(cent), 512 threads, KC=64, 2 stages
#define TM 128
#define TN 256
#define KC 64
#define NCHUNK (KDIM / KC)  // 28
#define ROWB 144            // bytes per smem row (64 bf16 + 8 pad)
#define STG ((TM + TN) * ROWB)   // 55296 per stage
#define BOFF (TM * ROWB)         // 18432: B rows after A rows
#define DIST_SMEM (2 * STG)      // 110592

// ---------------- scratch ----------------
__device__ float g_pool0[BATCH * 256 * 64 * 64];
__device__ float g_pool1[BATCH * 512 * 32 * 32];
__device__ float g_pool2[BATCH * 1024 * 16 * 16];
__device__ float g_conv1[BATCH * 512 * 32 * 32];   // pixel-major [b][pix][o]
__device__ float g_conv2[BATCH * 1024 * 16 * 16];  // pixel-major
__device__ __nv_bfloat16 g_phib[(size_t)BATCH * NPIX * KDIM];  // (b, pix, k)
__device__ __nv_bfloat16 g_Cb[(size_t)NCENT * KDIM];           // C^T (cent, k)
__device__ float g_feats[BATCH * NPIX];
__device__ float g_cents[NCENT];
__device__ float g_dist[(size_t)BATCH * NPIX * NCENT];  // squared distances
__device__ float g_wT1[258 * 256];
__device__ float g_wT2[514 * 512];
__device__ float g_wT3[1026 * 1024];

// ---------------- helpers ----------------
__device__ __forceinline__ uint32_t smem_u32(const void* p) {
    uint32_t a;
    asm("{ .reg .u64 t; cvta.to.shared.u64 t, %1; cvt.u32.u64 %0, t; }" : "=r"(a) : "l"(p));
    return a;
}
__device__ __forceinline__ void cpa16(uint32_t dst, const void* src) {
    asm volatile("cp.async.cg.shared.global [%0], [%1], 16;" ::"r"(dst), "l"(src));
}
__device__ __forceinline__ void ldsm4(uint32_t& r0, uint32_t& r1, uint32_t& r2, uint32_t& r3,
                                      uint32_t a) {
    asm volatile("ldmatrix.sync.aligned.m8n8.x4.shared.b16 {%0,%1,%2,%3}, [%4];"
                 : "=r"(r0), "=r"(r1), "=r"(r2), "=r"(r3)
                 : "r"(a));
}
__device__ __forceinline__ void mma_bf16(float* d, uint32_t a0, uint32_t a1, uint32_t a2,
                                         uint32_t a3, uint32_t b0, uint32_t b1) {
    asm volatile(
        "mma.sync.aligned.m16n8k16.row.col.f32.bf16.bf16.f32 "
        "{%0,%1,%2,%3}, {%4,%5,%6,%7}, {%8,%9}, {%0,%1,%2,%3};"
        : "+f"(d[0]), "+f"(d[1]), "+f"(d[2]), "+f"(d[3])
        : "r"(a0), "r"(a1), "r"(a2), "r"(a3), "r"(b0), "r"(b1));
}

// ---------------- level traits ----------------
template <int L> struct Lv {
    static constexpr int C = (L == 0) ? 256 : (L == 1) ? 512 : 1024;
    static constexpr int H = (L == 0) ? 64 : (L == 1) ? 32 : 16;
    static constexpr int PIX = H * H;
    static constexpr int CHOFF = (L == 0) ? 0 : (L == 1) ? 256 : 768;
};

// ---------------- 1) weight transpose ----------------
template <int L>
__global__ void wtrans_kernel(const float* __restrict__ w) {
    constexpr int CO = Lv<L>::C;
    constexpr int KI = CO + 2;
    float* wT = (L == 0) ? g_wT1 : (L == 1) ? g_wT2 : g_wT3;
    int i = blockIdx.x * blockDim.x + threadIdx.x;
    if (i >= CO * KI) return;
    int o = i / KI, k = i % KI;
    wT[k * CO + o] = w[i];
}

// ---------------- 2) avg_pool 3x3 /9 ----------------
template <int L>
__global__ void pool3_kernel(const float* __restrict__ x) {
    constexpr int C = Lv<L>::C, H = Lv<L>::H;
    float* y = (L == 0) ? g_pool0 : (L == 1) ? g_pool1 : g_pool2;
    int i = blockIdx.x * blockDim.x + threadIdx.x;
    constexpr int total = BATCH * C * H * H;
    if (i >= total) return;
    int w = i % H;
    int h = (i / H) % H;
    int bc = i / (H * H);
    const float* p = x + (size_t)bc * H * H;
    float s = 0.f;
#pragma unroll
    for (int dh = -1; dh <= 1; ++dh) {
        int hh = h + dh;
        if ((unsigned)hh < (unsigned)H) {
            const float* r = p + hh * H;
#pragma unroll
            for (int dw = -1; dw <= 1; ++dw) {
                int ww = w + dw;
                if ((unsigned)ww < (unsigned)H) s += r[ww];
            }
        }
    }
    y[i] = s * (1.0f / 9.0f);
}

// ---------------- 3) CoordConv 1x1 GEMM ----------------
template <int L>
__global__ __launch_bounds__(256) void conv1x1_kernel(const float* __restrict__ bias,
                                                      float* __restrict__ out) {
    constexpr int CI = Lv<L>::C, CO = CI, H = Lv<L>::H, PIX = Lv<L>::PIX;
    const float* pooled = (L == 0) ? g_pool0 : (L == 1) ? g_pool1 : g_pool2;
    const float* wT = (L == 0) ? g_wT1 : (L == 1) ? g_wT2 : g_wT3;
    float* convout = (L == 1) ? g_conv1 : g_conv2;

    int b = blockIdx.z;
    int oT = blockIdx.x * 64, pT = blockIdx.y * 64;
    __shared__ float As[16][64];
    __shared__ float Bs[16][64];
    int tid = threadIdx.x, tx = tid & 15, ty = tid >> 4;
    float acc[4][4] = {};
    const float* Ab = pooled + (size_t)b * CI * PIX;

    for (int kt = 0; kt < CI; kt += 16) {
        int lr = tid >> 4, lc = (tid & 15) * 4;
        *(float4*)&As[lr][lc] = *(const float4*)(Ab + (size_t)(kt + lr) * PIX + pT + lc);
        *(float4*)&Bs[lr][lc] = *(const float4*)(wT + (size_t)(kt + lr) * CO + oT + lc);
        __syncthreads();
#pragma unroll
        for (int k = 0; k < 16; k++) {
            float4 av = *(float4*)&As[k][ty * 4];
            float4 bv = *(float4*)&Bs[k][tx * 4];
            float a[4] = {av.x, av.y, av.z, av.w};
            float bb[4] = {bv.x, bv.y, bv.z, bv.w};
#pragma unroll
            for (int i2 = 0; i2 < 4; i2++)
#pragma unroll
                for (int j = 0; j < 4; j++) acc[i2][j] += a[i2] * bb[j];
        }
        __syncthreads();
    }

#pragma unroll
    for (int i2 = 0; i2 < 4; i2++) {
        int pix = pT + ty * 4 + i2;
        float xg = -1.0f + 2.0f * (float)(pix % H) / (float)(H - 1);
        float yg = -1.0f + 2.0f * (float)(pix / H) / (float)(H - 1);
        float v[4];
#pragma unroll
        for (int j = 0; j < 4; j++) {
            int o = oT + tx * 4 + j;
            v[j] = acc[i2][j] + bias[o] + wT[(size_t)CI * CO + o] * xg +
                   wT[(size_t)(CI + 1) * CO + o] * yg;
        }
        int o0 = oT + tx * 4;
        if (L == 0) {
            __nv_bfloat16 hv[4] = {__float2bfloat16(v[0]), __float2bfloat16(v[1]),
                                   __float2bfloat16(v[2]), __float2bfloat16(v[3])};
            *(uint2*)&g_phib[((size_t)(b * NPIX) + pix) * KDIM + o0] = *(uint2*)hv;
#pragma unroll
            for (int j = 0; j < 4; j++)
                out[SCORE_ELEMS + ((size_t)(b * PHI_OUT_C) + o0 + j) * NPIX + pix] = v[j];
        } else {
            *(float4*)&convout[((size_t)(b * PIX) + pix) * CO + o0] = *(float4*)v;
        }
    }
}

// ---------------- 4) bilinear resize, o-fastest ----------------
template <int L>
__global__ void resize_kernel(float* __restrict__ out) {
    constexpr int C = Lv<L>::C, H = Lv<L>::H, CHOFF = Lv<L>::CHOFF, PIX = Lv<L>::PIX;
    const float* conv = (L == 1) ? g_conv1 : g_conv2;
    int idx = blockIdx.x * blockDim.x + threadIdx.x;
    constexpr int total = BATCH * C * 4096 / 2;
    if (idx >= total) return;
    int o2 = (idx & (C / 2 - 1)) * 2;
    int rest = idx / (C / 2);
    int opix = rest & 4095;
    int b = rest >> 12;
    int ox = opix & 63, oy = opix >> 6;
    constexpr float scale = (float)H / 64.0f;
    float u = fmaxf((ox + 0.5f) * scale - 0.5f, 0.0f);
    float v = fmaxf((oy + 0.5f) * scale - 0.5f, 0.0f);
    int x0 = min((int)u, H - 1), y0 = min((int)v, H - 1);
    int x1 = min(x0 + 1, H - 1), y1 = min(y0 + 1, H - 1);
    float fx = u - (float)x0, fy = v - (float)y0;
    const float* p = conv + (size_t)(b * PIX) * C;
    float2 v00 = *(const float2*)&p[(size_t)(y0 * H + x0) * C + o2];
    float2 v01 = *(const float2*)&p[(size_t)(y0 * H + x1) * C + o2];
    float2 v10 = *(const float2*)&p[(size_t)(y1 * H + x0) * C + o2];
    float2 v11 = *(const float2*)&p[(size_t)(y1 * H + x1) * C + o2];
    float w00 = (1.f - fy) * (1.f - fx), w01 = (1.f - fy) * fx;
    float w10 = fy * (1.f - fx), w11 = fy * fx;
    float val0 = w00 * v00.x + w01 * v01.x + w10 * v10.x + w11 * v11.x;
    float val1 = w00 * v00.y + w01 * v01.y + w10 * v10.y + w11 * v11.y;
    __nv_bfloat16 hv[2] = {__float2bfloat16(val0), __float2bfloat16(val1)};
    *(uint32_t*)&g_phib[((size_t)(b * NPIX) + opix) * KDIM + CHOFF + o2] = *(uint32_t*)hv;
    int gc = CHOFF + o2;
    if (gc < PHI_OUT_C) {
        out[SCORE_ELEMS + ((size_t)(b * PHI_OUT_C) + gc) * NPIX + opix] = val0;
        out[SCORE_ELEMS + ((size_t)(b * PHI_OUT_C) + gc + 1) * NPIX + opix] = val1;
    }
}

// ---------------- 5) C transpose + feats / cents ----------------
__global__ void ctrans_kernel(const float* __restrict__ Cm) {
    __shared__ float tile[32][33];
    int nb = blockIdx.x * 32, kb = blockIdx.y * 32;
    int tx = threadIdx.x, ty = threadIdx.y;
    for (int r = ty; r < 32; r += 8)
        tile[r][tx] = Cm[(size_t)(kb + r) * NCENT + nb + tx];
    __syncthreads();
    for (int r = ty; r < 32; r += 8)
        g_Cb[(size_t)(nb + r) * KDIM + kb + tx] = __float2bfloat16(tile[tx][r]);
}

__global__ void feats_kernel() {
    int row = blockIdx.x;
    const __nv_bfloat16* p = g_phib + (size_t)row * KDIM;
    float s = 0.f;
    for (int k = threadIdx.x; k < KDIM; k += 256) {
        float v = __bfloat162float(p[k]);
        s += v * v;
    }
    __shared__ float sh[256];
    sh[threadIdx.x] = s;
    __syncthreads();
    for (int off = 128; off > 0; off >>= 1) {
        if (threadIdx.x < off) sh[threadIdx.x] += sh[threadIdx.x + off];
        __syncthreads();
    }
    if (threadIdx.x == 0) g_feats[row] = sh[0];
}

// cents from g_Cb rows (coalesced bf16): 1 warp -> 4 cents, 128 blocks x 8 warps
__global__ void cents_kernel() {
    int warp = threadIdx.x >> 5, lane = threadIdx.x & 31;
    int cent0 = blockIdx.x * 32 + warp * 4;
#pragma unroll
    for (int i = 0; i < 4; i++) {
        const __nv_bfloat16* p = g_Cb + (size_t)(cent0 + i) * KDIM;
        float s = 0.f;
#pragma unroll
        for (int it = 0; it < KDIM / 128; it++) {  // 14 iters of uint2 (4 bf16)
            uint2 v = *(const uint2*)(p + (size_t)(it * 32 + lane) * 4);
            __nv_bfloat16* h = (__nv_bfloat16*)&v;
#pragma unroll
            for (int q = 0; q < 4; q++) {
                float f = __bfloat162float(h[q]);
                s += f * f;
            }
        }
        for (int off = 16; off; off >>= 1) s += __shfl_down_sync(0xFFFFFFFFu, s, off);
        if (lane == 0) g_cents[cent0 + i] = s;
    }
}

// ---------------- 6) distance GEMM: 128x256, 512 thr, ldmatrix + mma.sync ----------------
__global__ __launch_bounds__(512, 1) void dist_mma_kernel() {
    extern __shared__ char ds[];
    uint32_t sbase = smem_u32(ds);

    int tid = threadIdx.x, wid = tid >> 5, lane = tid & 31;
    int wm = wid & 3, wn = wid >> 2;  // 4 x 4 warp grid; warp tile 32 x 64
    int b = blockIdx.z;
    int iT = blockIdx.y * TM;
    int jT = blockIdx.x * TN;

    const char* Abase = (const char*)(g_phib + (size_t)(b * NPIX + iT) * KDIM);
    const char* Bbase = (const char*)(g_Cb + (size_t)jT * KDIM);

    int crow = tid >> 3;   // 0..63
    int cc = tid & 7;

    int sub = lane >> 3, r8 = lane & 7;
    uint32_t aoff[2], boff[4];
#pragma unroll
    for (int mt = 0; mt < 2; mt++)
        aoff[mt] = (uint32_t)((wm * 32 + mt * 16 + (sub & 1) * 8 + r8) * ROWB + (sub >> 1) * 16);
#pragma unroll
    for (int nt2 = 0; nt2 < 4; nt2++)
        boff[nt2] = (uint32_t)(BOFF + (wn * 64 + nt2 * 16 + (sub >> 1) * 8 + r8) * ROWB +
                               (sub & 1) * 16);

    float acc[2][8][4];
#pragma unroll
    for (int mt = 0; mt < 2; mt++)
#pragma unroll
        for (int nt = 0; nt < 8; nt++)
#pragma unroll
            for (int q = 0; q < 4; q++) acc[mt][nt][q] = 0.0f;

#define ISSUE_CHUNK(i, buf)                                                                \
    do {                                                                                   \
        uint32_t st_ = sbase + (buf) * STG;                                                \
        _Pragma("unroll") for (int q = 0; q < 2; q++) {                                    \
            int row = crow + q * 64;                                                       \
            cpa16(st_ + row * ROWB + cc * 16,                                              \
                  Abase + ((size_t)row * KDIM + (size_t)(i) * KC + cc * 8) * 2);           \
        }                                                                                  \
        _Pragma("unroll") for (int q = 0; q < 4; q++) {                                    \
            int row = crow + q * 64;                                                       \
            cpa16(st_ + BOFF + row * ROWB + cc * 16,                                       \
                  Bbase + ((size_t)row * KDIM + (size_t)(i) * KC + cc * 8) * 2);           \
        }                                                                                  \
        asm volatile("cp.async.commit_group;");                                            \
    } while (0)

    ISSUE_CHUNK(0, 0);

    for (int i = 0; i < NCHUNK; i++) {
        int buf = i & 1;
        if (i + 1 < NCHUNK) {
            ISSUE_CHUNK(i + 1, (i + 1) & 1);
            asm volatile("cp.async.wait_group 1;");
        } else {
            asm volatile("cp.async.wait_group 0;");
        }
        __syncthreads();

        uint32_t st = sbase + buf * STG;
#pragma unroll
        for (int ks = 0; ks < 4; ks++) {
            uint32_t bf[8][2];
#pragma unroll
            for (int nt2 = 0; nt2 < 4; nt2++)
                ldsm4(bf[nt2 * 2][0], bf[nt2 * 2][1], bf[nt2 * 2 + 1][0], bf[nt2 * 2 + 1][1],
                      st + boff[nt2] + ks * 32);
#pragma unroll
            for (int mt = 0; mt < 2; mt++) {
                uint32_t a0, a1, a2, a3;
                ldsm4(a0, a1, a2, a3, st + aoff[mt] + ks * 32);
#pragma unroll
                for (int nt = 0; nt < 8; nt++)
                    mma_bf16(acc[mt][nt], a0, a1, a2, a3, bf[nt][0], bf[nt][1]);
            }
        }
        __syncthreads();
    }
#undef ISSUE_CHUNK

    // epilogue: store squared distance (sqrt deferred to select)
    int g = lane >> 2, c2 = (lane & 3) * 2;
#pragma unroll
    for (int mt = 0; mt < 2; mt++) {
        int gr = iT + wm * 32 + mt * 16 + g;
        float f0 = g_feats[b * NPIX + gr];
        float f1 = g_feats[b * NPIX + gr + 8];
        float* row0 = g_dist + (size_t)(b * NPIX + gr) * NCENT;
        float* row1 = g_dist + (size_t)(b * NPIX + gr + 8) * NCENT;
#pragma unroll
        for (int nt = 0; nt < 8; nt++) {
            int gc = jT + wn * 64 + nt * 8 + c2;
            float ce0 = __ldg(&g_cents[gc]);
            float ce1 = __ldg(&g_cents[gc + 1]);
            float2 v0, v1;
            v0.x = fmaxf(f0 + ce0 - 2.0f * acc[mt][nt][0], 0.0f);
            v0.y = fmaxf(f0 + ce1 - 2.0f * acc[mt][nt][1], 0.0f);
            v1.x = fmaxf(f1 + ce0 - 2.0f * acc[mt][nt][2], 0.0f);
            v1.y = fmaxf(f1 + ce1 - 2.0f * acc[mt][nt][3], 0.0f);
            *(float2*)(row0 + gc) = v0;
            *(float2*)(row1 + gc) = v1;
        }
    }
}

// ---------------- 7) top-200 per row: radix-select + bitonic sort ----------------
__global__ __launch_bounds__(256) void select_kernel(float* __restrict__ out) {
    int row = blockIdx.x;
    int b = row >> 12;
    int pix = row & 4095;
    const float* d = g_dist + (size_t)row * NCENT;
    int t = threadIdx.x;
    int lane = t & 31;

    unsigned key[16];
#pragma unroll
    for (int j = 0; j < 16; j++) key[j] = __float_as_uint(d[t + j * 256]);

    // 4-pass radix: find exact key (T) of the 200th smallest
    __shared__ int hist[256];
    __shared__ unsigned s_sel;
    __shared__ int s_need;
    unsigned prefix = 0;
    int need = TOPK;
    for (int pass = 0; pass < 4; pass++) {
        int shift = 24 - pass * 8;
        hist[t] = 0;
        __syncthreads();
#pragma unroll
        for (int j = 0; j < 16; j++) {
            unsigned k = key[j];
            bool ok = (pass == 0) ? true : ((k >> (shift + 8)) == prefix);
            if (ok) atomicAdd(&hist[(k >> shift) & 255], 1);
        }
        __syncthreads();
        // warp 0: inclusive scan of 256 bins (8 bins per lane)
        if (t < 32) {
            int v8[8];
            int run = 0;
#pragma unroll
            for (int q = 0; q < 8; q++) {
                run += hist[t * 8 + q];
                v8[q] = run;
            }
            int v = run;
            for (int off = 1; off < 32; off <<= 1) {
                int u = __shfl_up_sync(0xFFFFFFFFu, v, off);
                if (lane >= off) v += u;
            }
            int ex = v - run;
#pragma unroll
            for (int q = 0; q < 8; q++) hist[t * 8 + q] = v8[q] + ex;
        }
        __syncthreads();
        int cum = hist[t];
        int prev = (t == 0) ? 0 : hist[t - 1];
        if (prev < need && need <= cum) {
            s_sel = (unsigned)t;
            s_need = need - prev;
        }
        __syncthreads();
        prefix = (prefix << 8) | s_sel;
        need = s_need;
    }
    unsigned T = prefix;  // exact 200th-smallest key

    // gather values < T (count <= 199), pad with T
    __shared__ unsigned cand[256];
    __shared__ int s_cnt;
    cand[t] = T;
    if (t == 0) s_cnt = 0;
    __syncthreads();
#pragma unroll
    for (int j = 0; j < 16; j++) {
        if (key[j] < T) {
            int p = atomicAdd(&s_cnt, 1);
            if (p < 256) cand[p] = key[j];
        }
    }
    __syncthreads();

    // bitonic sort 256 ascending
    for (int k = 2; k <= 256; k <<= 1) {
        for (int j = k >> 1; j > 0; j >>= 1) {
            int ixj = t ^ j;
            if (ixj > t) {
                unsigned a = cand[t], z = cand[ixj];
                bool up = ((t & k) == 0);
                if ((a > z) == up) {
                    cand[t] = z;
                    cand[ixj] = a;
                }
            }
            __syncthreads();
        }
    }

    if (t < TOPK)
        out[((size_t)(b * TOPK) + t) * NPIX + pix] = sqrtf(__uint_as_float(cand[t]));
}

// ---------------- launch ----------------
extern "C" void kernel_launch(void* const* d_in, const int* in_sizes, int n_in,
                              void* d_out, int out_size) {
    const float* p0 = (const float*)d_in[0];
    const float* p1 = (const float*)d_in[1];
    const float* p2 = (const float*)d_in[2];
    const float* w1 = (const float*)d_in[5];
    const float* b1 = (const float*)d_in[6];
    const float* w2 = (const float*)d_in[7];
    const float* b2 = (const float*)d_in[8];
    const float* w3 = (const float*)d_in[9];
    const float* b3 = (const float*)d_in[10];
    const float* Cm = (const float*)d_in[11];
    float* out = (float*)d_out;

    cudaFuncSetAttribute(dist_mma_kernel, cudaFuncAttributeMaxDynamicSharedMemorySize,
                         DIST_SMEM);

    wtrans_kernel<0><<<(256 * 258 + 255) / 256, 256>>>(w1);
    wtrans_kernel<1><<<(512 * 514 + 255) / 256, 256>>>(w2);
    wtrans_kernel<2><<<(1024 * 1026 + 255) / 256, 256>>>(w3);

    pool3_kernel<0><<<(BATCH * 256 * 64 * 64) / 256, 256>>>(p0);
    pool3_kernel<1><<<(BATCH * 512 * 32 * 32) / 256, 256>>>(p1);
    pool3_kernel<2><<<(BATCH * 1024 * 16 * 16) / 256, 256>>>(p2);

    conv1x1_kernel<0><<<dim3(256 / 64, 4096 / 64, BATCH), 256>>>(b1, out);
    conv1x1_kernel<1><<<dim3(512 / 64, 1024 / 64, BATCH), 256>>>(b2, out);
    conv1x1_kernel<2><<<dim3(1024 / 64, 256 / 64, BATCH), 256>>>(b3, out);

    resize_kernel<1><<<(BATCH * 512 * 4096 / 2 + 255) / 256, 256>>>(out);
    resize_kernel<2><<<(BATCH * 1024 * 4096 / 2 + 255) / 256, 256>>>(out);

    ctrans_kernel<<<dim3(NCENT / 32, KDIM / 32), dim3(32, 8)>>>(Cm);

    feats_kernel<<<BATCH * NPIX, 256>>>();
    cents_kernel<<<NCENT / 32, 256>>>();

    dist_mma_kernel<<<dim3(NCENT / TN, NPIX / TM, BATCH), 512, DIST_SMEM>>>();

    select_kernel<<<BATCH * NPIX, 256>>>(out);
}

// round 6
// speedup vs baseline: 5.7313x; 1.4466x over previous
#include <cuda_runtime.h>
#include <cuda_bf16.h>
#include <cstdint>

#define BATCH 4
#define KDIM 1792
#define NPIX 4096
#define NCENT 4096
#define TOPK 200
#define PHI_OUT_C 896
#define SCORE_ELEMS (BATCH * TOPK * NPIX)

// dist GEMM tiling: 128x128, 256 thr, int8 KC=128 bytes, 2 stages
#define TM 128
#define TN 128
#define KC 128
#define NCHUNK (KDIM / KC)  // 14
#define ROWB 144            // 128 data bytes + 16 pad
#define STG ((TM + TN) * ROWB)  // 36864
#define BOFF (TM * ROWB)        // 18432
#define DIST_SMEM (2 * STG)     // 73728

// ---------------- scratch ----------------
__device__ float g_pool0[BATCH * 256 * 64 * 64];
__device__ float g_pool1[BATCH * 512 * 32 * 32];
__device__ float g_pool2[BATCH * 1024 * 16 * 16];
__device__ float g_conv1[BATCH * 512 * 32 * 32];   // pixel-major [b][pix][o]
__device__ float g_conv2[BATCH * 1024 * 16 * 16];  // pixel-major
__device__ __nv_bfloat16 g_phib[(size_t)BATCH * NPIX * KDIM];  // (b, pix, k)
__device__ __nv_bfloat16 g_Cb[(size_t)NCENT * KDIM];           // C^T (cent, k)
__device__ signed char g_phii[(size_t)BATCH * NPIX * KDIM];
__device__ signed char g_Ci[(size_t)NCENT * KDIM];
__device__ float g_sA[BATCH * NPIX];
__device__ float g_sB[NCENT];
__device__ float g_feats[BATCH * NPIX];
__device__ float g_cents[NCENT];
__device__ float g_dist[(size_t)BATCH * NPIX * NCENT];  // squared distances
__device__ float g_wT1[258 * 256];
__device__ float g_wT2[514 * 512];
__device__ float g_wT3[1026 * 1024];

// ---------------- helpers ----------------
__device__ __forceinline__ uint32_t smem_u32(const void* p) {
    uint32_t a;
    asm("{ .reg .u64 t; cvta.to.shared.u64 t, %1; cvt.u32.u64 %0, t; }" : "=r"(a) : "l"(p));
    return a;
}
__device__ __forceinline__ void cpa16(uint32_t dst, const void* src) {
    asm volatile("cp.async.cg.shared.global [%0], [%1], 16;" ::"r"(dst), "l"(src));
}
__device__ __forceinline__ void ldsm4(uint32_t& r0, uint32_t& r1, uint32_t& r2, uint32_t& r3,
                                      uint32_t a) {
    asm volatile("ldmatrix.sync.aligned.m8n8.x4.shared.b16 {%0,%1,%2,%3}, [%4];"
                 : "=r"(r0), "=r"(r1), "=r"(r2), "=r"(r3)
                 : "r"(a));
}
__device__ __forceinline__ void mma_s8(int* d, uint32_t a0, uint32_t a1, uint32_t a2,
                                       uint32_t a3, uint32_t b0, uint32_t b1) {
    asm volatile(
        "mma.sync.aligned.m16n8k32.row.col.s32.s8.s8.s32 "
        "{%0,%1,%2,%3}, {%4,%5,%6,%7}, {%8,%9}, {%0,%1,%2,%3};"
        : "+r"(d[0]), "+r"(d[1]), "+r"(d[2]), "+r"(d[3])
        : "r"(a0), "r"(a1), "r"(a2), "r"(a3), "r"(b0), "r"(b1));
}

// ---------------- level traits ----------------
template <int L> struct Lv {
    static constexpr int C = (L == 0) ? 256 : (L == 1) ? 512 : 1024;
    static constexpr int H = (L == 0) ? 64 : (L == 1) ? 32 : 16;
    static constexpr int PIX = H * H;
    static constexpr int CHOFF = (L == 0) ? 0 : (L == 1) ? 256 : 768;
};

// ---------------- 1) weight transpose ----------------
template <int L>
__global__ void wtrans_kernel(const float* __restrict__ w) {
    constexpr int CO = Lv<L>::C;
    constexpr int KI = CO + 2;
    float* wT = (L == 0) ? g_wT1 : (L == 1) ? g_wT2 : g_wT3;
    int i = blockIdx.x * blockDim.x + threadIdx.x;
    if (i >= CO * KI) return;
    int o = i / KI, k = i % KI;
    wT[k * CO + o] = w[i];
}

// ---------------- 2) avg_pool 3x3 /9 ----------------
template <int L>
__global__ void pool3_kernel(const float* __restrict__ x) {
    constexpr int C = Lv<L>::C, H = Lv<L>::H;
    float* y = (L == 0) ? g_pool0 : (L == 1) ? g_pool1 : g_pool2;
    int i = blockIdx.x * blockDim.x + threadIdx.x;
    constexpr int total = BATCH * C * H * H;
    if (i >= total) return;
    int w = i % H;
    int h = (i / H) % H;
    int bc = i / (H * H);
    const float* p = x + (size_t)bc * H * H;
    float s = 0.f;
#pragma unroll
    for (int dh = -1; dh <= 1; ++dh) {
        int hh = h + dh;
        if ((unsigned)hh < (unsigned)H) {
            const float* r = p + hh * H;
#pragma unroll
            for (int dw = -1; dw <= 1; ++dw) {
                int ww = w + dw;
                if ((unsigned)ww < (unsigned)H) s += r[ww];
            }
        }
    }
    y[i] = s * (1.0f / 9.0f);
}

// ---------------- 3) CoordConv 1x1 GEMM ----------------
template <int L>
__global__ __launch_bounds__(256) void conv1x1_kernel(const float* __restrict__ bias,
                                                      float* __restrict__ out) {
    constexpr int CI = Lv<L>::C, CO = CI, H = Lv<L>::H, PIX = Lv<L>::PIX;
    const float* pooled = (L == 0) ? g_pool0 : (L == 1) ? g_pool1 : g_pool2;
    const float* wT = (L == 0) ? g_wT1 : (L == 1) ? g_wT2 : g_wT3;
    float* convout = (L == 1) ? g_conv1 : g_conv2;

    int b = blockIdx.z;
    int oT = blockIdx.x * 64, pT = blockIdx.y * 64;
    __shared__ float As[16][64];
    __shared__ float Bs[16][64];
    int tid = threadIdx.x, tx = tid & 15, ty = tid >> 4;
    float acc[4][4] = {};
    const float* Ab = pooled + (size_t)b * CI * PIX;

    for (int kt = 0; kt < CI; kt += 16) {
        int lr = tid >> 4, lc = (tid & 15) * 4;
        *(float4*)&As[lr][lc] = *(const float4*)(Ab + (size_t)(kt + lr) * PIX + pT + lc);
        *(float4*)&Bs[lr][lc] = *(const float4*)(wT + (size_t)(kt + lr) * CO + oT + lc);
        __syncthreads();
#pragma unroll
        for (int k = 0; k < 16; k++) {
            float4 av = *(float4*)&As[k][ty * 4];
            float4 bv = *(float4*)&Bs[k][tx * 4];
            float a[4] = {av.x, av.y, av.z, av.w};
            float bb[4] = {bv.x, bv.y, bv.z, bv.w};
#pragma unroll
            for (int i2 = 0; i2 < 4; i2++)
#pragma unroll
                for (int j = 0; j < 4; j++) acc[i2][j] += a[i2] * bb[j];
        }
        __syncthreads();
    }

#pragma unroll
    for (int i2 = 0; i2 < 4; i2++) {
        int pix = pT + ty * 4 + i2;
        float xg = -1.0f + 2.0f * (float)(pix % H) / (float)(H - 1);
        float yg = -1.0f + 2.0f * (float)(pix / H) / (float)(H - 1);
        float v[4];
#pragma unroll
        for (int j = 0; j < 4; j++) {
            int o = oT + tx * 4 + j;
            v[j] = acc[i2][j] + bias[o] + wT[(size_t)CI * CO + o] * xg +
                   wT[(size_t)(CI + 1) * CO + o] * yg;
        }
        int o0 = oT + tx * 4;
        if (L == 0) {
            __nv_bfloat16 hv[4] = {__float2bfloat16(v[0]), __float2bfloat16(v[1]),
                                   __float2bfloat16(v[2]), __float2bfloat16(v[3])};
            *(uint2*)&g_phib[((size_t)(b * NPIX) + pix) * KDIM + o0] = *(uint2*)hv;
#pragma unroll
            for (int j = 0; j < 4; j++)
                out[SCORE_ELEMS + ((size_t)(b * PHI_OUT_C) + o0 + j) * NPIX + pix] = v[j];
        } else {
            *(float4*)&convout[((size_t)(b * PIX) + pix) * CO + o0] = *(float4*)v;
        }
    }
}

// ---------------- 4) bilinear resize, o-fastest ----------------
template <int L>
__global__ void resize_kernel(float* __restrict__ out) {
    constexpr int C = Lv<L>::C, H = Lv<L>::H, CHOFF = Lv<L>::CHOFF, PIX = Lv<L>::PIX;
    const float* conv = (L == 1) ? g_conv1 : g_conv2;
    int idx = blockIdx.x * blockDim.x + threadIdx.x;
    constexpr int total = BATCH * C * 4096 / 2;
    if (idx >= total) return;
    int o2 = (idx & (C / 2 - 1)) * 2;
    int rest = idx / (C / 2);
    int opix = rest & 4095;
    int b = rest >> 12;
    int ox = opix & 63, oy = opix >> 6;
    constexpr float scale = (float)H / 64.0f;
    float u = fmaxf((ox + 0.5f) * scale - 0.5f, 0.0f);
    float v = fmaxf((oy + 0.5f) * scale - 0.5f, 0.0f);
    int x0 = min((int)u, H - 1), y0 = min((int)v, H - 1);
    int x1 = min(x0 + 1, H - 1), y1 = min(y0 + 1, H - 1);
    float fx = u - (float)x0, fy = v - (float)y0;
    const float* p = conv + (size_t)(b * PIX) * C;
    float2 v00 = *(const float2*)&p[(size_t)(y0 * H + x0) * C + o2];
    float2 v01 = *(const float2*)&p[(size_t)(y0 * H + x1) * C + o2];
    float2 v10 = *(const float2*)&p[(size_t)(y1 * H + x0) * C + o2];
    float2 v11 = *(const float2*)&p[(size_t)(y1 * H + x1) * C + o2];
    float w00 = (1.f - fy) * (1.f - fx), w01 = (1.f - fy) * fx;
    float w10 = fy * (1.f - fx), w11 = fy * fx;
    float val0 = w00 * v00.x + w01 * v01.x + w10 * v10.x + w11 * v11.x;
    float val1 = w00 * v00.y + w01 * v01.y + w10 * v10.y + w11 * v11.y;
    __nv_bfloat16 hv[2] = {__float2bfloat16(val0), __float2bfloat16(val1)};
    *(uint32_t*)&g_phib[((size_t)(b * NPIX) + opix) * KDIM + CHOFF + o2] = *(uint32_t*)hv;
    int gc = CHOFF + o2;
    if (gc < PHI_OUT_C) {
        out[SCORE_ELEMS + ((size_t)(b * PHI_OUT_C) + gc) * NPIX + opix] = val0;
        out[SCORE_ELEMS + ((size_t)(b * PHI_OUT_C) + gc + 1) * NPIX + opix] = val1;
    }
}

// ---------------- 5) C transpose (fp32 -> bf16 cent-major) ----------------
__global__ void ctrans_kernel(const float* __restrict__ Cm) {
    __shared__ float tile[32][33];
    int nb = blockIdx.x * 32, kb = blockIdx.y * 32;
    int tx = threadIdx.x, ty = threadIdx.y;
    for (int r = ty; r < 32; r += 8)
        tile[r][tx] = Cm[(size_t)(kb + r) * NCENT + nb + tx];
    __syncthreads();
    for (int r = ty; r < 32; r += 8)
        g_Cb[(size_t)(nb + r) * KDIM + kb + tx] = __float2bfloat16(tile[tx][r]);
}

// ---------------- 6) per-row int8 quantization + exact norms ----------------
// feats/cents computed FROM quantized values: dist^2 becomes an exact metric.
template <int ISPHI>
__global__ __launch_bounds__(256) void quant_kernel() {
    int row = blockIdx.x;
    const __nv_bfloat16* src = (ISPHI ? g_phib : g_Cb) + (size_t)row * KDIM;
    signed char* dst = (ISPHI ? g_phii : g_Ci) + (size_t)row * KDIM;
    int t = threadIdx.x;

    float v[7];
    float mx = 0.f;
#pragma unroll
    for (int j = 0; j < 7; j++) {
        v[j] = __bfloat162float(src[t + j * 256]);
        mx = fmaxf(mx, fabsf(v[j]));
    }
    // block max
    for (int off = 16; off; off >>= 1)
        mx = fmaxf(mx, __shfl_xor_sync(0xFFFFFFFFu, mx, off));
    __shared__ float shm[8];
    __shared__ float s_mx;
    if ((t & 31) == 0) shm[t >> 5] = mx;
    __syncthreads();
    if (t == 0) {
        float m = shm[0];
        for (int w = 1; w < 8; w++) m = fmaxf(m, shm[w]);
        s_mx = m;
    }
    __syncthreads();
    float rowmax = s_mx;
    float inv = (rowmax > 0.f) ? (127.0f / rowmax) : 0.f;
    float scale = (rowmax > 0.f) ? (rowmax / 127.0f) : 0.f;

    int ss = 0;
#pragma unroll
    for (int j = 0; j < 7; j++) {
        int q = __float2int_rn(v[j] * inv);
        dst[t + j * 256] = (signed char)q;
        ss += q * q;
    }
    for (int off = 16; off; off >>= 1) ss += __shfl_xor_sync(0xFFFFFFFFu, ss, off);
    __shared__ int shs[8];
    if ((t & 31) == 0) shs[t >> 5] = ss;
    __syncthreads();
    if (t == 0) {
        int s = 0;
        for (int w = 0; w < 8; w++) s += shs[w];
        float norm = scale * scale * (float)s;
        if (ISPHI) {
            g_sA[row] = scale;
            g_feats[row] = norm;
        } else {
            g_sB[row] = scale;
            g_cents[row] = norm;
        }
    }
}

// ---------------- 7) distance GEMM: int8 mma.sync, 128x128, 2 CTA/SM ----------------
__global__ __launch_bounds__(256, 2) void dist_mma_kernel() {
    extern __shared__ char ds[];
    uint32_t sbase = smem_u32(ds);

    int tid = threadIdx.x, wid = tid >> 5, lane = tid & 31;
    int wm = wid & 3, wn = wid >> 2;  // 4m x 2n warp grid; warp tile 32 x 64
    int b = blockIdx.z;
    int iT = blockIdx.y * TM;
    int jT = blockIdx.x * TN;

    const char* Abase = (const char*)(g_phii + (size_t)(b * NPIX + iT) * KDIM);
    const char* Bbase = (const char*)(g_Ci + (size_t)jT * KDIM);

    int crow = tid >> 3;  // 0..31
    int cc = tid & 7;

    int sub = lane >> 3, r8 = lane & 7;
    uint32_t aoff[2], boff[4];
#pragma unroll
    for (int mt = 0; mt < 2; mt++)
        aoff[mt] = (uint32_t)((wm * 32 + mt * 16 + (sub & 1) * 8 + r8) * ROWB + (sub >> 1) * 16);
#pragma unroll
    for (int nt2 = 0; nt2 < 4; nt2++)
        boff[nt2] = (uint32_t)(BOFF + (wn * 64 + nt2 * 16 + (sub >> 1) * 8 + r8) * ROWB +
                               (sub & 1) * 16);

    int acc[2][8][4];
#pragma unroll
    for (int mt = 0; mt < 2; mt++)
#pragma unroll
        for (int nt = 0; nt < 8; nt++)
#pragma unroll
            for (int q = 0; q < 4; q++) acc[mt][nt][q] = 0;

#define ISSUE_CHUNK(i, buf)                                                        \
    do {                                                                           \
        uint32_t st_ = sbase + (buf) * STG;                                        \
        _Pragma("unroll") for (int q = 0; q < 4; q++) {                            \
            int row = crow + q * 32;                                               \
            cpa16(st_ + row * ROWB + cc * 16,                                      \
                  Abase + (size_t)row * KDIM + (size_t)(i) * KC + cc * 16);        \
            cpa16(st_ + BOFF + row * ROWB + cc * 16,                               \
                  Bbase + (size_t)row * KDIM + (size_t)(i) * KC + cc * 16);        \
        }                                                                          \
        asm volatile("cp.async.commit_group;");                                    \
    } while (0)

    ISSUE_CHUNK(0, 0);

    for (int i = 0; i < NCHUNK; i++) {
        int buf = i & 1;
        if (i + 1 < NCHUNK) {
            ISSUE_CHUNK(i + 1, (i + 1) & 1);
            asm volatile("cp.async.wait_group 1;");
        } else {
            asm volatile("cp.async.wait_group 0;");
        }
        __syncthreads();

        uint32_t st = sbase + buf * STG;
#pragma unroll
        for (int ks = 0; ks < 4; ks++) {  // k32 per step, 4 steps = 128 bytes
            uint32_t bf[8][2];
#pragma unroll
            for (int nt2 = 0; nt2 < 4; nt2++)
                ldsm4(bf[nt2 * 2][0], bf[nt2 * 2][1], bf[nt2 * 2 + 1][0], bf[nt2 * 2 + 1][1],
                      st + boff[nt2] + ks * 32);
#pragma unroll
            for (int mt = 0; mt < 2; mt++) {
                uint32_t a0, a1, a2, a3;
                ldsm4(a0, a1, a2, a3, st + aoff[mt] + ks * 32);
#pragma unroll
                for (int nt = 0; nt < 8; nt++)
                    mma_s8(acc[mt][nt], a0, a1, a2, a3, bf[nt][0], bf[nt][1]);
            }
        }
        __syncthreads();
    }
#undef ISSUE_CHUNK

    // epilogue: d^2 = feats + cents - 2*sA*sB*acc  (exact metric of quantized points)
    int g = lane >> 2, c2 = (lane & 3) * 2;
#pragma unroll
    for (int mt = 0; mt < 2; mt++) {
        int gr = iT + wm * 32 + mt * 16 + g;
        float f0 = g_feats[b * NPIX + gr];
        float f1 = g_feats[b * NPIX + gr + 8];
        float sa0 = g_sA[b * NPIX + gr];
        float sa1 = g_sA[b * NPIX + gr + 8];
        float* row0 = g_dist + (size_t)(b * NPIX + gr) * NCENT;
        float* row1 = g_dist + (size_t)(b * NPIX + gr + 8) * NCENT;
#pragma unroll
        for (int nt = 0; nt < 8; nt++) {
            int gc = jT + wn * 64 + nt * 8 + c2;
            float ce0 = __ldg(&g_cents[gc]);
            float ce1 = __ldg(&g_cents[gc + 1]);
            float sb0 = __ldg(&g_sB[gc]);
            float sb1 = __ldg(&g_sB[gc + 1]);
            float2 v0, v1;
            v0.x = fmaxf(fmaf(-2.0f * sa0 * sb0, (float)acc[mt][nt][0], f0 + ce0), 0.0f);
            v0.y = fmaxf(fmaf(-2.0f * sa0 * sb1, (float)acc[mt][nt][1], f0 + ce1), 0.0f);
            v1.x = fmaxf(fmaf(-2.0f * sa1 * sb0, (float)acc[mt][nt][2], f1 + ce0), 0.0f);
            v1.y = fmaxf(fmaf(-2.0f * sa1 * sb1, (float)acc[mt][nt][3], f1 + ce1), 0.0f);
            *(float2*)(row0 + gc) = v0;
            *(float2*)(row1 + gc) = v1;
        }
    }
}

// ---------------- 8) top-200 per row: radix-select + bitonic sort ----------------
__global__ __launch_bounds__(256) void select_kernel(float* __restrict__ out) {
    int row = blockIdx.x;
    int b = row >> 12;
    int pix = row & 4095;
    const float* d = g_dist + (size_t)row * NCENT;
    int t = threadIdx.x;
    int lane = t & 31;

    unsigned key[16];
#pragma unroll
    for (int j = 0; j < 16; j++) key[j] = __float_as_uint(d[t + j * 256]);

    __shared__ int hist[256];
    __shared__ unsigned s_sel;
    __shared__ int s_need;
    unsigned prefix = 0;
    int need = TOPK;
    for (int pass = 0; pass < 4; pass++) {
        int shift = 24 - pass * 8;
        hist[t] = 0;
        __syncthreads();
#pragma unroll
        for (int j = 0; j < 16; j++) {
            unsigned k = key[j];
            bool ok = (pass == 0) ? true : ((k >> (shift + 8)) == prefix);
            if (ok) atomicAdd(&hist[(k >> shift) & 255], 1);
        }
        __syncthreads();
        if (t < 32) {
            int v8[8];
            int run = 0;
#pragma unroll
            for (int q = 0; q < 8; q++) {
                run += hist[t * 8 + q];
                v8[q] = run;
            }
            int v = run;
            for (int off = 1; off < 32; off <<= 1) {
                int u = __shfl_up_sync(0xFFFFFFFFu, v, off);
                if (lane >= off) v += u;
            }
            int ex = v - run;
#pragma unroll
            for (int q = 0; q < 8; q++) hist[t * 8 + q] = v8[q] + ex;
        }
        __syncthreads();
        int cum = hist[t];
        int prev = (t == 0) ? 0 : hist[t - 1];
        if (prev < need && need <= cum) {
            s_sel = (unsigned)t;
            s_need = need - prev;
        }
        __syncthreads();
        prefix = (prefix << 8) | s_sel;
        need = s_need;
    }
    unsigned T = prefix;

    __shared__ unsigned cand[256];
    __shared__ int s_cnt;
    cand[t] = T;
    if (t == 0) s_cnt = 0;
    __syncthreads();
#pragma unroll
    for (int j = 0; j < 16; j++) {
        if (key[j] < T) {
            int p = atomicAdd(&s_cnt, 1);
            if (p < 256) cand[p] = key[j];
        }
    }
    __syncthreads();

    for (int k = 2; k <= 256; k <<= 1) {
        for (int j = k >> 1; j > 0; j >>= 1) {
            int ixj = t ^ j;
            if (ixj > t) {
                unsigned a = cand[t], z = cand[ixj];
                bool up = ((t & k) == 0);
                if ((a > z) == up) {
                    cand[t] = z;
                    cand[ixj] = a;
                }
            }
            __syncthreads();
        }
    }

    if (t < TOPK)
        out[((size_t)(b * TOPK) + t) * NPIX + pix] = sqrtf(__uint_as_float(cand[t]));
}

// ---------------- launch ----------------
extern "C" void kernel_launch(void* const* d_in, const int* in_sizes, int n_in,
                              void* d_out, int out_size) {
    const float* p0 = (const float*)d_in[0];
    const float* p1 = (const float*)d_in[1];
    const float* p2 = (const float*)d_in[2];
    const float* w1 = (const float*)d_in[5];
    const float* b1 = (const float*)d_in[6];
    const float* w2 = (const float*)d_in[7];
    const float* b2 = (const float*)d_in[8];
    const float* w3 = (const float*)d_in[9];
    const float* b3 = (const float*)d_in[10];
    const float* Cm = (const float*)d_in[11];
    float* out = (float*)d_out;

    cudaFuncSetAttribute(dist_mma_kernel, cudaFuncAttributeMaxDynamicSharedMemorySize,
                         DIST_SMEM);

    wtrans_kernel<0><<<(256 * 258 + 255) / 256, 256>>>(w1);
    wtrans_kernel<1><<<(512 * 514 + 255) / 256, 256>>>(w2);
    wtrans_kernel<2><<<(1024 * 1026 + 255) / 256, 256>>>(w3);

    pool3_kernel<0><<<(BATCH * 256 * 64 * 64) / 256, 256>>>(p0);
    pool3_kernel<1><<<(BATCH * 512 * 32 * 32) / 256, 256>>>(p1);
    pool3_kernel<2><<<(BATCH * 1024 * 16 * 16) / 256, 256>>>(p2);

    conv1x1_kernel<0><<<dim3(256 / 64, 4096 / 64, BATCH), 256>>>(b1, out);
    conv1x1_kernel<1><<<dim3(512 / 64, 1024 / 64, BATCH), 256>>>(b2, out);
    conv1x1_kernel<2><<<dim3(1024 / 64, 256 / 64, BATCH), 256>>>(b3, out);

    resize_kernel<1><<<(BATCH * 512 * 4096 / 2 + 255) / 256, 256>>>(out);
    resize_kernel<2><<<(BATCH * 1024 * 4096 / 2 + 255) / 256, 256>>>(out);

    ctrans_kernel<<<dim3(NCENT / 32, KDIM / 32), dim3(32, 8)>>>(Cm);

    quant_kernel<1><<<BATCH * NPIX, 256>>>();  // phi -> int8 + feats + sA
    quant_kernel<0><<<NCENT, 256>>>();         // C   -> int8 + cents + sB

    dist_mma_kernel<<<dim3(NCENT / TN, NPIX / TM, BATCH), 256, DIST_SMEM>>>();

    select_kernel<<<BATCH * NPIX, 256>>>(out);
}